// round 3
// baseline (speedup 1.0000x reference)
#include <cuda_runtime.h>

#define BB    8
#define NH    12
#define NTOK  1025
#define FT    768
#define FH    64
#define MROWS (BB*NTOK)   /* 8200 */
#define NDIST 3972

// ---- static scratch (no allocations allowed) ----
__device__ float g_q[(size_t)BB*NH*NTOK*FH];
__device__ float g_k[(size_t)BB*NH*NTOK*FH];
__device__ float g_v[(size_t)BB*NH*NTOK*FH];
__device__ float g_ao[(size_t)MROWS*FT];

// ============================================================
// Kernel 1: QKV GEMM.  C[m, c] = sum_k tokens[m,k] * qkv_w[c,k]
// Fused epilogue: scatter into q/k/v (b,h,n,f) layouts with
// q-bias + 1/sqrt(d) scale and v-bias applied.
// ============================================================
__global__ __launch_bounds__(256) void qkv_gemm(
        const float* __restrict__ A, const float* __restrict__ W,
        const float* __restrict__ qb, const float* __restrict__ vb)
{
    __shared__ float As[16][64];   // [k][m]
    __shared__ float Bs[16][64];   // [k][n]
    const int tid = threadIdx.x;
    const int tx = tid & 15, ty = tid >> 4;
    const int m0 = blockIdx.y * 64, n0 = blockIdx.x * 64;
    const int lm = tid >> 2;          // 0..63
    const int lk = (tid & 3) << 2;    // 0,4,8,12

    float acc[4][4] = {};
    for (int k0 = 0; k0 < FT; k0 += 16) {
        float4 a4 = make_float4(0.f, 0.f, 0.f, 0.f);
        if (m0 + lm < MROWS)
            a4 = *(const float4*)(A + (size_t)(m0 + lm) * FT + k0 + lk);
        As[lk+0][lm] = a4.x; As[lk+1][lm] = a4.y;
        As[lk+2][lm] = a4.z; As[lk+3][lm] = a4.w;
        float4 b4 = *(const float4*)(W + (size_t)(n0 + lm) * FT + k0 + lk);
        Bs[lk+0][lm] = b4.x; Bs[lk+1][lm] = b4.y;
        Bs[lk+2][lm] = b4.z; Bs[lk+3][lm] = b4.w;
        __syncthreads();
        #pragma unroll
        for (int k = 0; k < 16; k++) {
            float4 ra = *(const float4*)&As[k][ty << 2];
            float4 rb = *(const float4*)&Bs[k][tx << 2];
            float av[4] = {ra.x, ra.y, ra.z, ra.w};
            float bv[4] = {rb.x, rb.y, rb.z, rb.w};
            #pragma unroll
            for (int i = 0; i < 4; i++)
                #pragma unroll
                for (int j = 0; j < 4; j++)
                    acc[i][j] += av[i] * bv[j];
        }
        __syncthreads();
    }
    #pragma unroll
    for (int i = 0; i < 4; i++) {
        int m = m0 + (ty << 2) + i;
        if (m >= MROWS) break;
        int b = m / NTOK, n = m - b * NTOK;
        #pragma unroll
        for (int j = 0; j < 4; j++) {
            int c = n0 + (tx << 2) + j;
            int part = c / FT;
            int hc = c - part * FT;          // h*64 + f
            int h = hc >> 6, f = hc & 63;
            size_t o = ((size_t)(b * NH + h) * NTOK + n) * FH + f;
            float v = acc[i][j];
            if (part == 0)      g_q[o] = (v + qb[hc]) * 0.125f;
            else if (part == 1) g_k[o] = v;
            else                g_v[o] = v + vb[hc];
        }
    }
}

// ============================================================
// Kernel 2: fused flash-attention with relpos bias gather.
// One CTA = (b, h, 64-row Q tile). Online softmax over 17 key
// tiles of 64. Bias gathered per-element from relpos_index (L2)
// + relpos_table (L1).
// ============================================================
__global__ __launch_bounds__(256) void attn_kernel(
        const float* __restrict__ table, const int* __restrict__ rpi)
{
    __shared__ float Qt[64][64];   // [f][row]     (Q transposed)
    __shared__ float KV[64][64];   // K: [f][key]  then V: [key][f]
    __shared__ float Ps[64][64];   // [row][key]
    const int tid = threadIdx.x;
    const int tx = tid & 15, ty = tid >> 4;
    const int b = blockIdx.z, h = blockIdx.y;
    const int q0 = blockIdx.x * 64;
    const float* Qg = g_q + (size_t)(b * NH + h) * NTOK * FH;
    const float* Kg = g_k + (size_t)(b * NH + h) * NTOK * FH;
    const float* Vg = g_v + (size_t)(b * NH + h) * NTOK * FH;

    const int lrow = tid >> 2;           // 0..63
    const int lcol = (tid & 3) << 2;     // 0,4,8,12

    // load Q tile transposed: Qt[f][row]
    #pragma unroll
    for (int s = 0; s < 4; s++) {
        int f = lcol + s * 16;
        float4 v = make_float4(0.f, 0.f, 0.f, 0.f);
        if (q0 + lrow < NTOK)
            v = *(const float4*)(Qg + (size_t)(q0 + lrow) * FH + f);
        Qt[f+0][lrow] = v.x; Qt[f+1][lrow] = v.y;
        Qt[f+2][lrow] = v.z; Qt[f+3][lrow] = v.w;
    }

    float O[4][4] = {};
    float mr[4], ls[4];
    #pragma unroll
    for (int i = 0; i < 4; i++) { mr[i] = -1e30f; ls[i] = 0.f; }

    for (int jt = 0; jt < 17; jt++) {
        const int k0 = jt * 64;
        __syncthreads();                       // Q ready / prev PV done with KV
        // load K transposed: KV[f][key]
        #pragma unroll
        for (int s = 0; s < 4; s++) {
            int f = lcol + s * 16;
            float4 v = make_float4(0.f, 0.f, 0.f, 0.f);
            if (k0 + lrow < NTOK)
                v = *(const float4*)(Kg + (size_t)(k0 + lrow) * FH + f);
            KV[f+0][lrow] = v.x; KV[f+1][lrow] = v.y;
            KV[f+2][lrow] = v.z; KV[f+3][lrow] = v.w;
        }
        __syncthreads();
        // S = Q K^T (4x4 per thread)
        float S[4][4] = {};
        #pragma unroll 8
        for (int f = 0; f < 64; f++) {
            float4 ra = *(const float4*)&Qt[f][ty << 2];
            float4 rb = *(const float4*)&KV[f][tx << 2];
            float av[4] = {ra.x, ra.y, ra.z, ra.w};
            float bv[4] = {rb.x, rb.y, rb.z, rb.w};
            #pragma unroll
            for (int i = 0; i < 4; i++)
                #pragma unroll
                for (int j = 0; j < 4; j++)
                    S[i][j] += av[i] * bv[j];
        }
        // relpos bias + mask
        #pragma unroll
        for (int i = 0; i < 4; i++) {
            int qi = q0 + (ty << 2) + i;
            #pragma unroll
            for (int j = 0; j < 4; j++) {
                int kj = k0 + (tx << 2) + j;
                if (qi < NTOK && kj < NTOK)
                    S[i][j] += table[(size_t)rpi[(size_t)qi * NTOK + kj] * NH + h];
                else
                    S[i][j] = -1e30f;
            }
        }
        // online softmax update (row groups live on 16 lanes: lane bits 0..3 = tx)
        #pragma unroll
        for (int i = 0; i < 4; i++) {
            float rm = fmaxf(fmaxf(S[i][0], S[i][1]), fmaxf(S[i][2], S[i][3]));
            #pragma unroll
            for (int o = 8; o > 0; o >>= 1)
                rm = fmaxf(rm, __shfl_xor_sync(0xffffffffu, rm, o));
            float mnew = fmaxf(mr[i], rm);
            float alpha = __expf(mr[i] - mnew);
            mr[i] = mnew;
            float rs = 0.f;
            #pragma unroll
            for (int j = 0; j < 4; j++) {
                S[i][j] = __expf(S[i][j] - mnew);
                rs += S[i][j];
            }
            #pragma unroll
            for (int o = 8; o > 0; o >>= 1)
                rs += __shfl_xor_sync(0xffffffffu, rs, o);
            ls[i] = ls[i] * alpha + rs;
            #pragma unroll
            for (int j = 0; j < 4; j++) O[i][j] *= alpha;
        }
        __syncthreads();                       // everyone done reading KV as K
        // write P; load V into KV as [key][f]
        #pragma unroll
        for (int i = 0; i < 4; i++)
            #pragma unroll
            for (int j = 0; j < 4; j++)
                Ps[(ty << 2) + i][(tx << 2) + j] = S[i][j];
        #pragma unroll
        for (int s = 0; s < 4; s++) {
            int f = lcol + s * 16;
            float4 v = make_float4(0.f, 0.f, 0.f, 0.f);
            if (k0 + lrow < NTOK)
                v = *(const float4*)(Vg + (size_t)(k0 + lrow) * FH + f);
            *(float4*)&KV[lrow][f] = v;
        }
        __syncthreads();
        // O += P V
        #pragma unroll 8
        for (int k = 0; k < 64; k++) {
            float pv[4];
            #pragma unroll
            for (int i = 0; i < 4; i++) pv[i] = Ps[(ty << 2) + i][k];
            float4 rv = *(const float4*)&KV[k][tx << 2];
            float vv[4] = {rv.x, rv.y, rv.z, rv.w};
            #pragma unroll
            for (int i = 0; i < 4; i++)
                #pragma unroll
                for (int j = 0; j < 4; j++)
                    O[i][j] += pv[i] * vv[j];
        }
    }
    // epilogue: normalize, write (b, n, h*64+f)
    #pragma unroll
    for (int i = 0; i < 4; i++) {
        int qi = q0 + (ty << 2) + i;
        if (qi >= NTOK) break;
        float inv = 1.f / ls[i];
        #pragma unroll
        for (int j = 0; j < 4; j++)
            g_ao[(size_t)(b * NTOK + qi) * FT + h * FH + (tx << 2) + j]
                = O[i][j] * inv;
    }
}

// ============================================================
// Kernel 3: output projection. out[m,n] = sum_k ao[m,k]*proj_w[n,k] + b[n]
// ============================================================
__global__ __launch_bounds__(256) void proj_gemm(
        const float* __restrict__ W, const float* __restrict__ bias,
        float* __restrict__ out)
{
    __shared__ float As[16][64];
    __shared__ float Bs[16][64];
    const int tid = threadIdx.x;
    const int tx = tid & 15, ty = tid >> 4;
    const int m0 = blockIdx.y * 64, n0 = blockIdx.x * 64;
    const int lm = tid >> 2;
    const int lk = (tid & 3) << 2;

    float acc[4][4] = {};
    for (int k0 = 0; k0 < FT; k0 += 16) {
        float4 a4 = make_float4(0.f, 0.f, 0.f, 0.f);
        if (m0 + lm < MROWS)
            a4 = *(const float4*)(g_ao + (size_t)(m0 + lm) * FT + k0 + lk);
        As[lk+0][lm] = a4.x; As[lk+1][lm] = a4.y;
        As[lk+2][lm] = a4.z; As[lk+3][lm] = a4.w;
        float4 b4 = *(const float4*)(W + (size_t)(n0 + lm) * FT + k0 + lk);
        Bs[lk+0][lm] = b4.x; Bs[lk+1][lm] = b4.y;
        Bs[lk+2][lm] = b4.z; Bs[lk+3][lm] = b4.w;
        __syncthreads();
        #pragma unroll
        for (int k = 0; k < 16; k++) {
            float4 ra = *(const float4*)&As[k][ty << 2];
            float4 rb = *(const float4*)&Bs[k][tx << 2];
            float av[4] = {ra.x, ra.y, ra.z, ra.w};
            float bv[4] = {rb.x, rb.y, rb.z, rb.w};
            #pragma unroll
            for (int i = 0; i < 4; i++)
                #pragma unroll
                for (int j = 0; j < 4; j++)
                    acc[i][j] += av[i] * bv[j];
        }
        __syncthreads();
    }
    #pragma unroll
    for (int i = 0; i < 4; i++) {
        int m = m0 + (ty << 2) + i;
        if (m >= MROWS) break;
        #pragma unroll
        for (int j = 0; j < 4; j++) {
            int c = n0 + (tx << 2) + j;
            out[(size_t)m * FT + c] = acc[i][j] + bias[c];
        }
    }
}

// ============================================================
extern "C" void kernel_launch(void* const* d_in, const int* in_sizes, int n_in,
                              void* d_out, int out_size)
{
    const float* tokens = (const float*)d_in[0];
    const float* qkv_w  = (const float*)d_in[1];
    const float* q_bias = (const float*)d_in[2];
    const float* v_bias = (const float*)d_in[3];
    const float* table  = (const float*)d_in[4];
    const float* proj_w = (const float*)d_in[5];
    const float* proj_b = (const float*)d_in[6];
    const int*   rpi    = (const int*)d_in[7];
    float* out = (float*)d_out;

    dim3 blk(256);
    dim3 g1((3 * FT) / 64, (MROWS + 63) / 64);   // 36 x 129
    qkv_gemm<<<g1, blk>>>(tokens, qkv_w, q_bias, v_bias);

    dim3 g2((NTOK + 63) / 64, NH, BB);           // 17 x 12 x 8
    attn_kernel<<<g2, blk>>>(table, rpi);

    dim3 g3(FT / 64, (MROWS + 63) / 64);         // 12 x 129
    proj_gemm<<<g3, blk>>>(proj_w, proj_b, out);
}

// round 5
// speedup vs baseline: 1.0064x; 1.0064x over previous
#include <cuda_runtime.h>

#define BB    8
#define NH    12
#define NTOK  1025
#define FT    768
#define FH    64
#define MROWS (BB*NTOK)   /* 8200 */

// ---- static scratch (no allocations allowed) ----
__device__ float g_q[(size_t)BB*NH*NTOK*FH];
__device__ float g_k[(size_t)BB*NH*NTOK*FH];
__device__ float g_v[(size_t)BB*NH*NTOK*FH];
__device__ float g_ao[(size_t)MROWS*FT];

// ---- packed fp32x2 helpers ----
__device__ __forceinline__ void ffma2(unsigned long long &c, unsigned long long a, unsigned long long b){
    asm volatile("fma.rn.f32x2 %0, %1, %2, %0;" : "+l"(c) : "l"(a), "l"(b));
}
__device__ __forceinline__ void mul2(unsigned long long &c, unsigned long long a){
    asm volatile("mul.rn.f32x2 %0, %0, %1;" : "+l"(c) : "l"(a));
}
__device__ __forceinline__ unsigned long long dup2(float x){
    unsigned long long r;
    asm("mov.b64 %0, {%1, %1};" : "=l"(r) : "r"(__float_as_uint(x)));
    return r;
}
__device__ __forceinline__ float2 unpack2(unsigned long long v){
    unsigned int lo, hi;
    asm("mov.b64 {%0, %1}, %2;" : "=r"(lo), "=r"(hi) : "l"(v));
    return make_float2(__uint_as_float(lo), __uint_as_float(hi));
}

// ============================================================
// GEMM: C[m,c] = sum_k A[m,k] * W[c,k].  128x128x8 tiles, FFMA2.
// EPI=0: A = Ain (tokens), qkv scatter epilogue.
// EPI=1: A = g_ao (DEVICE-side symbol!), proj + bias epilogue.
// ============================================================
template<int EPI>
__global__ __launch_bounds__(256,2) void gemm128(
        const float* __restrict__ Ain, const float* __restrict__ W,
        const float* __restrict__ p0, const float* __restrict__ p1,
        float* __restrict__ outp)
{
    __shared__ float As2[2][8][256];   // [buf][k][2m] duplicated A
    __shared__ float Bs [2][8][128];   // [buf][k][n]  plain B

    // BUGFIX vs R4: g_ao must be resolved in DEVICE code, not passed from host.
    const float* A = (EPI == 0) ? Ain : (const float*)g_ao;

    const int tid = threadIdx.x;
    const int tx = tid & 15, ty = tid >> 4;
    const int m0 = blockIdx.y * 128, n0 = blockIdx.x * 128;

    const int lm = tid & 127;             // row within tile (A) / col (B)
    const int lkq = (tid >> 7) * 4;       // k quad base (0 or 4)
    const float* Ap = A + (size_t)(m0 + lm) * FT + lkq;
    const float* Wp = W + (size_t)(n0 + lm) * FT + lkq;
    const bool aval = (m0 + lm) < MROWS;

    unsigned long long acc[8][4];
    #pragma unroll
    for (int i = 0; i < 8; i++)
        #pragma unroll
        for (int j = 0; j < 4; j++) acc[i][j] = 0ull;

    // preload step 0
    float4 ra = aval ? *(const float4*)Ap : make_float4(0.f,0.f,0.f,0.f);
    float4 rb = *(const float4*)Wp;
    {
        float av[4] = {ra.x, ra.y, ra.z, ra.w};
        float bv[4] = {rb.x, rb.y, rb.z, rb.w};
        #pragma unroll
        for (int i = 0; i < 4; i++) {
            *(float2*)&As2[0][lkq+i][2*lm] = make_float2(av[i], av[i]);
            Bs[0][lkq+i][lm] = bv[i];
        }
    }
    __syncthreads();

    const int NSTEPS = FT / 8;  // 96
    int buf = 0;
    for (int s = 0; s < NSTEPS; s++) {
        float4 na, nb;
        if (s + 1 < NSTEPS) {
            na = aval ? *(const float4*)(Ap + (s+1)*8) : make_float4(0.f,0.f,0.f,0.f);
            nb = *(const float4*)(Wp + (s+1)*8);
        }
        #pragma unroll
        for (int k = 0; k < 8; k++) {
            const float* arow = &As2[buf][k][0];
            const float* brow = &Bs[buf][k][0];
            ulonglong2 aA = *(const ulonglong2*)(arow + ty*8);
            ulonglong2 aB = *(const ulonglong2*)(arow + ty*8 + 4);
            ulonglong2 aC = *(const ulonglong2*)(arow + 128 + ty*8);
            ulonglong2 aD = *(const ulonglong2*)(arow + 128 + ty*8 + 4);
            ulonglong2 b0 = *(const ulonglong2*)(brow + tx*4);
            ulonglong2 b1 = *(const ulonglong2*)(brow + 64 + tx*4);
            unsigned long long av[8] = {aA.x,aA.y,aB.x,aB.y,aC.x,aC.y,aD.x,aD.y};
            unsigned long long bv[4] = {b0.x,b0.y,b1.x,b1.y};
            #pragma unroll
            for (int i = 0; i < 8; i++)
                #pragma unroll
                for (int j = 0; j < 4; j++)
                    ffma2(acc[i][j], av[i], bv[j]);
        }
        if (s + 1 < NSTEPS) {
            buf ^= 1;
            float av[4] = {na.x, na.y, na.z, na.w};
            float bv[4] = {nb.x, nb.y, nb.z, nb.w};
            #pragma unroll
            for (int i = 0; i < 4; i++) {
                *(float2*)&As2[buf][lkq+i][2*lm] = make_float2(av[i], av[i]);
                Bs[buf][lkq+i][lm] = bv[i];
            }
        }
        __syncthreads();
    }

    // epilogue
    const int cb[4] = {tx*4, tx*4+2, 64+tx*4, 64+tx*4+2};
    #pragma unroll
    for (int i = 0; i < 8; i++) {
        int r = m0 + ty*4 + (i & 3) + ((i >> 2) << 6);
        if (r >= MROWS) continue;
        if (EPI == 0) {
            int b = r / NTOK, n = r - b * NTOK;
            #pragma unroll
            for (int j = 0; j < 4; j++) {
                float2 v = unpack2(acc[i][j]);
                int c = n0 + cb[j];
                int part = c / FT;
                int hc = c - part * FT;
                int hh = hc >> 6, f = hc & 63;
                size_t o = ((size_t)(b * NH + hh) * NTOK + n) * FH + f;
                if (part == 0) {
                    float2 rr = make_float2((v.x + p0[hc]) * 0.125f,
                                            (v.y + p0[hc+1]) * 0.125f);
                    *(float2*)&g_q[o] = rr;
                } else if (part == 1) {
                    *(float2*)&g_k[o] = v;
                } else {
                    float2 rr = make_float2(v.x + p1[hc], v.y + p1[hc+1]);
                    *(float2*)&g_v[o] = rr;
                }
            }
        } else {
            #pragma unroll
            for (int j = 0; j < 4; j++) {
                float2 v = unpack2(acc[i][j]);
                int c = n0 + cb[j];
                float2 rr = make_float2(v.x + p0[c], v.y + p0[c+1]);
                *(float2*)&outp[(size_t)r * FT + c] = rr;
            }
        }
    }
}

// ============================================================
// Fused flash-attention with relpos bias, FFMA2 inner loops.
// CTA = (b, h, 64-row Q tile), 17 key tiles of 64, online softmax.
// smem: Qd[64][128] dup | KtV[64][68] (K [f][key] then V [key][f]) | Pd[64][130] dup
// ============================================================
#define KTV_S 68
#define PD_S  130
#define SMEM_ATTN ((64*128 + 64*KTV_S + 64*PD_S) * 4)

__global__ __launch_bounds__(256,2) void attn_kernel(
        const float* __restrict__ table, const int* __restrict__ rpi)
{
    extern __shared__ float sm[];
    float (*Qd)[128]   = (float(*)[128])sm;
    float (*KtV)[KTV_S] = (float(*)[KTV_S])(sm + 64*128);
    float (*Pd)[PD_S]  = (float(*)[PD_S])(sm + 64*128 + 64*KTV_S);

    const int tid = threadIdx.x;
    const int tx = tid & 15, ty = tid >> 4;
    const int b = blockIdx.z, h = blockIdx.y;
    const int q0 = blockIdx.x * 64;
    const float* Qg = g_q + (size_t)(b * NH + h) * NTOK * FH;
    const float* Kg = g_k + (size_t)(b * NH + h) * NTOK * FH;
    const float* Vg = g_v + (size_t)(b * NH + h) * NTOK * FH;

    const int lrow = tid >> 2;            // 0..63
    const int lfb  = (tid & 3) << 2;      // 0,4,8,12

    // load Q duplicated: Qd[f][2*row]
    #pragma unroll
    for (int s = 0; s < 4; s++) {
        int f = lfb + s * 16;
        float4 v = make_float4(0.f,0.f,0.f,0.f);
        if (q0 + lrow < NTOK)
            v = *(const float4*)(Qg + (size_t)(q0 + lrow) * FH + f);
        float vv[4] = {v.x, v.y, v.z, v.w};
        #pragma unroll
        for (int i = 0; i < 4; i++)
            *(float2*)&Qd[f+i][2*lrow] = make_float2(vv[i], vv[i]);
    }

    unsigned long long O2[4][2];
    float mr[4], ls[4];
    #pragma unroll
    for (int i = 0; i < 4; i++) {
        O2[i][0] = 0ull; O2[i][1] = 0ull;
        mr[i] = -1e30f; ls[i] = 0.f;
    }

    for (int jt = 0; jt < 17; jt++) {
        const int k0 = jt * 64;
        __syncthreads();                 // prev PV done with KtV & Pd; Q ready
        // load K transposed: KtV[f][key]
        #pragma unroll
        for (int s = 0; s < 4; s++) {
            int f = lfb + s * 16;
            float4 v = make_float4(0.f,0.f,0.f,0.f);
            if (k0 + lrow < NTOK)
                v = *(const float4*)(Kg + (size_t)(k0 + lrow) * FH + f);
            KtV[f+0][lrow] = v.x; KtV[f+1][lrow] = v.y;
            KtV[f+2][lrow] = v.z; KtV[f+3][lrow] = v.w;
        }
        __syncthreads();

        // S = Q K^T : 4 rows x 2 col-pairs per thread
        unsigned long long S2[4][2];
        #pragma unroll
        for (int i = 0; i < 4; i++) { S2[i][0] = 0ull; S2[i][1] = 0ull; }
        #pragma unroll 8
        for (int f = 0; f < 64; f++) {
            ulonglong2 qa = *(const ulonglong2*)&Qd[f][ty*8];      // rows ty*4, +1 (dup)
            ulonglong2 qb = *(const ulonglong2*)&Qd[f][ty*8 + 4];  // rows +2, +3 (dup)
            ulonglong2 kk = *(const ulonglong2*)&KtV[f][tx*4];     // key pairs
            unsigned long long av[4] = {qa.x, qa.y, qb.x, qb.y};
            #pragma unroll
            for (int i = 0; i < 4; i++) {
                ffma2(S2[i][0], av[i], kk.x);
                ffma2(S2[i][1], av[i], kk.y);
            }
        }

        // bias + online softmax + write P (duplicated)
        #pragma unroll
        for (int i = 0; i < 4; i++) {
            int qi = q0 + ty*4 + i;
            float2 u0 = unpack2(S2[i][0]), u1 = unpack2(S2[i][1]);
            float sc[4] = {u0.x, u0.y, u1.x, u1.y};
            #pragma unroll
            for (int j = 0; j < 4; j++) {
                int kj = k0 + tx*4 + j;
                if (qi < NTOK && kj < NTOK)
                    sc[j] += table[(size_t)rpi[(size_t)qi * NTOK + kj] * NH + h];
                else
                    sc[j] = -1e30f;
            }
            float rm = fmaxf(fmaxf(sc[0], sc[1]), fmaxf(sc[2], sc[3]));
            #pragma unroll
            for (int o = 8; o > 0; o >>= 1)
                rm = fmaxf(rm, __shfl_xor_sync(0xffffffffu, rm, o));
            float mnew = fmaxf(mr[i], rm);
            float alpha = __expf(mr[i] - mnew);
            mr[i] = mnew;
            float rs = 0.f;
            #pragma unroll
            for (int j = 0; j < 4; j++) {
                sc[j] = __expf(sc[j] - mnew);
                rs += sc[j];
            }
            #pragma unroll
            for (int o = 8; o > 0; o >>= 1)
                rs += __shfl_xor_sync(0xffffffffu, rs, o);
            ls[i] = ls[i] * alpha + rs;
            unsigned long long al2 = dup2(alpha);
            mul2(O2[i][0], al2);
            mul2(O2[i][1], al2);
            #pragma unroll
            for (int j = 0; j < 4; j++)
                *(float2*)&Pd[ty*4 + i][2*(tx*4 + j)] = make_float2(sc[j], sc[j]);
        }
        __syncthreads();                 // all done reading KtV as K

        // load V into KtV region as [key][f]
        #pragma unroll
        for (int s = 0; s < 4; s++) {
            int f = lfb + s * 16;
            float4 v = make_float4(0.f,0.f,0.f,0.f);
            if (k0 + lrow < NTOK)
                v = *(const float4*)(Vg + (size_t)(k0 + lrow) * FH + f);
            *(float4*)&KtV[lrow][f] = v;
        }
        __syncthreads();

        // O += P V
        #pragma unroll 8
        for (int k = 0; k < 64; k++) {
            unsigned long long p0 = *(const unsigned long long*)&Pd[ty*4+0][2*k];
            unsigned long long p1 = *(const unsigned long long*)&Pd[ty*4+1][2*k];
            unsigned long long p2 = *(const unsigned long long*)&Pd[ty*4+2][2*k];
            unsigned long long p3 = *(const unsigned long long*)&Pd[ty*4+3][2*k];
            ulonglong2 vv = *(const ulonglong2*)&KtV[k][tx*4];
            ffma2(O2[0][0], p0, vv.x); ffma2(O2[0][1], p0, vv.y);
            ffma2(O2[1][0], p1, vv.x); ffma2(O2[1][1], p1, vv.y);
            ffma2(O2[2][0], p2, vv.x); ffma2(O2[2][1], p2, vv.y);
            ffma2(O2[3][0], p3, vv.x); ffma2(O2[3][1], p3, vv.y);
        }
    }

    // epilogue
    #pragma unroll
    for (int i = 0; i < 4; i++) {
        int qi = q0 + ty*4 + i;
        if (qi >= NTOK) continue;
        float inv = 1.f / ls[i];
        float2 a = unpack2(O2[i][0]);
        float2 c = unpack2(O2[i][1]);
        float* dst = g_ao + (size_t)(b * NTOK + qi) * FT + h * FH + tx*4;
        *(float2*)(dst)     = make_float2(a.x * inv, a.y * inv);
        *(float2*)(dst + 2) = make_float2(c.x * inv, c.y * inv);
    }
}

// ============================================================
extern "C" void kernel_launch(void* const* d_in, const int* in_sizes, int n_in,
                              void* d_out, int out_size)
{
    const float* tokens = (const float*)d_in[0];
    const float* qkv_w  = (const float*)d_in[1];
    const float* q_bias = (const float*)d_in[2];
    const float* v_bias = (const float*)d_in[3];
    const float* table  = (const float*)d_in[4];
    const float* proj_w = (const float*)d_in[5];
    const float* proj_b = (const float*)d_in[6];
    const int*   rpi    = (const int*)d_in[7];
    float* out = (float*)d_out;

    cudaFuncSetAttribute(attn_kernel,
                         cudaFuncAttributeMaxDynamicSharedMemorySize, SMEM_ATTN);

    dim3 blk(256);
    dim3 g1((3 * FT) / 128, (MROWS + 127) / 128);   // 18 x 65
    gemm128<0><<<g1, blk>>>(tokens, qkv_w, q_bias, v_bias, nullptr);

    dim3 g2((NTOK + 63) / 64, NH, BB);              // 17 x 12 x 8
    attn_kernel<<<g2, blk, SMEM_ATTN>>>(table, rpi);

    dim3 g3(FT / 128, (MROWS + 127) / 128);         // 6 x 65
    gemm128<1><<<g3, blk>>>(nullptr, proj_w, proj_b, nullptr, out);
}

// round 6
// speedup vs baseline: 1.4002x; 1.3913x over previous
#include <cuda_runtime.h>

#define BB    8
#define NH    12
#define NTOK  1025
#define FT    768
#define FH    64
#define MROWS (BB*NTOK)   /* 8200 */
#define BPAD  1088        /* padded bias row (covers kj up to 1087) */

// ---- static scratch (no allocations allowed) ----
__device__ float g_q[(size_t)BB*NH*NTOK*FH];
__device__ float g_k[(size_t)BB*NH*NTOK*FH];
__device__ float g_v[(size_t)BB*NH*NTOK*FH];
__device__ float g_ao[(size_t)MROWS*FT];
__device__ float g_bias[(size_t)NH*NTOK*BPAD];   /* ~53 MB */

// ---- packed fp32x2 helpers (attention kernel) ----
__device__ __forceinline__ void ffma2(unsigned long long &c, unsigned long long a, unsigned long long b){
    asm volatile("fma.rn.f32x2 %0, %1, %2, %0;" : "+l"(c) : "l"(a), "l"(b));
}
__device__ __forceinline__ void mul2(unsigned long long &c, unsigned long long a){
    asm volatile("mul.rn.f32x2 %0, %0, %1;" : "+l"(c) : "l"(a));
}
__device__ __forceinline__ unsigned long long dup2(float x){
    unsigned long long r;
    asm("mov.b64 %0, {%1, %1};" : "=l"(r) : "r"(__float_as_uint(x)));
    return r;
}
__device__ __forceinline__ float2 unpack2(unsigned long long v){
    unsigned int lo, hi;
    asm("mov.b64 {%0, %1}, %2;" : "=r"(lo), "=r"(hi) : "l"(v));
    return make_float2(__uint_as_float(lo), __uint_as_float(hi));
}

// ---- tf32 mma helpers ----
__device__ __forceinline__ unsigned f2tf32(float x){
    unsigned r; asm("cvt.rna.tf32.f32 %0, %1;" : "=r"(r) : "f"(x)); return r;
}
__device__ __forceinline__ void mma_tf32(float* c,
        unsigned a0, unsigned a1, unsigned a2, unsigned a3,
        unsigned b0, unsigned b1){
    asm volatile(
        "mma.sync.aligned.m16n8k8.row.col.f32.tf32.tf32.f32 "
        "{%0,%1,%2,%3}, {%4,%5,%6,%7}, {%8,%9}, {%0,%1,%2,%3};"
        : "+f"(c[0]), "+f"(c[1]), "+f"(c[2]), "+f"(c[3])
        : "r"(a0), "r"(a1), "r"(a2), "r"(a3), "r"(b0), "r"(b1));
}

// ============================================================
// Kernel 0: precompute relpos bias  g_bias[h][qi][kj]
// ============================================================
__global__ __launch_bounds__(256) void bias_pre(
        const float* __restrict__ table, const int* __restrict__ rpi)
{
    const int qi = blockIdx.x, h = blockIdx.y;
    const int* row = rpi + (size_t)qi * NTOK;
    float* dst = g_bias + ((size_t)h * NTOK + qi) * BPAD;
    for (int kj = threadIdx.x; kj < NTOK; kj += 256)
        dst[kj] = table[(size_t)row[kj] * NH + h];
}

// ============================================================
// TF32 tensor-core GEMM: C[m,c] = sum_k A[m,k] * W[c,k]
// 128x128 CTA tile, kstep 16, 8 warps (4m x 2n), warp tile 32x64.
// EPI=0: A = tokens, qkv scatter epilogue (bias+scale fused).
// EPI=1: A = g_ao (device symbol), proj + bias epilogue.
// ============================================================
template<int EPI>
__global__ __launch_bounds__(256,2) void gemm_tf32(
        const float* __restrict__ Ain, const float* __restrict__ W,
        const float* __restrict__ p0, const float* __restrict__ p1,
        float* __restrict__ outp)
{
    __shared__ unsigned As[2][16][136];
    __shared__ unsigned Bs[2][16][136];

    const float* A = (EPI == 0) ? Ain : (const float*)g_ao;

    const int tid  = threadIdx.x;
    const int lane = tid & 31, wid = tid >> 5;
    const int warp_m = wid & 3, warp_n = wid >> 2;      // 4 x 2
    const int m_base = warp_m * 32, n_basew = warp_n * 64;
    const int grp = lane >> 2, krw = lane & 3;
    const int m0 = blockIdx.y * 128, n0 = blockIdx.x * 128;

    const int lm = tid & 127;            // row (A) / col (B) loaded by this thread
    const int kq = (tid >> 7) * 8;       // k offset 0 or 8
    const float* Ap = A + (size_t)(m0 + lm) * FT + kq;
    const float* Wp = W + (size_t)(n0 + lm) * FT + kq;
    const bool aval = (m0 + lm) < MROWS;

    float acc[2][8][4];
    #pragma unroll
    for (int mt = 0; mt < 2; mt++)
        #pragma unroll
        for (int nt = 0; nt < 8; nt++)
            #pragma unroll
            for (int q = 0; q < 4; q++) acc[mt][nt][q] = 0.f;

    // preload k-step 0
    {
        float4 a0 = aval ? *(const float4*)(Ap)     : make_float4(0,0,0,0);
        float4 a1 = aval ? *(const float4*)(Ap + 4) : make_float4(0,0,0,0);
        float4 b0 = *(const float4*)(Wp);
        float4 b1 = *(const float4*)(Wp + 4);
        float av[8] = {a0.x,a0.y,a0.z,a0.w, a1.x,a1.y,a1.z,a1.w};
        float bv[8] = {b0.x,b0.y,b0.z,b0.w, b1.x,b1.y,b1.z,b1.w};
        #pragma unroll
        for (int t = 0; t < 8; t++) {
            As[0][kq + t][lm] = f2tf32(av[t]);
            Bs[0][kq + t][lm] = f2tf32(bv[t]);
        }
    }
    __syncthreads();

    const int NSTEPS = FT / 16;   // 48
    int buf = 0;
    for (int s = 0; s < NSTEPS; s++) {
        float4 na0, na1, nb0, nb1;
        if (s + 1 < NSTEPS) {
            const float* ap = Ap + (s + 1) * 16;
            const float* wp = Wp + (s + 1) * 16;
            na0 = aval ? *(const float4*)(ap)     : make_float4(0,0,0,0);
            na1 = aval ? *(const float4*)(ap + 4) : make_float4(0,0,0,0);
            nb0 = *(const float4*)(wp);
            nb1 = *(const float4*)(wp + 4);
        }
        #pragma unroll
        for (int ks = 0; ks < 16; ks += 8) {
            unsigned b0[8], b1[8];
            #pragma unroll
            for (int nt = 0; nt < 8; nt++) {
                int col = n_basew + nt * 8 + grp;
                b0[nt] = Bs[buf][ks + krw][col];
                b1[nt] = Bs[buf][ks + krw + 4][col];
            }
            #pragma unroll
            for (int mt = 0; mt < 2; mt++) {
                int row = m_base + mt * 16 + grp;
                unsigned a0 = As[buf][ks + krw][row];
                unsigned a1 = As[buf][ks + krw][row + 8];
                unsigned a2 = As[buf][ks + krw + 4][row];
                unsigned a3 = As[buf][ks + krw + 4][row + 8];
                #pragma unroll
                for (int nt = 0; nt < 8; nt++)
                    mma_tf32(acc[mt][nt], a0, a1, a2, a3, b0[nt], b1[nt]);
            }
        }
        if (s + 1 < NSTEPS) {
            buf ^= 1;
            float av[8] = {na0.x,na0.y,na0.z,na0.w, na1.x,na1.y,na1.z,na1.w};
            float bv[8] = {nb0.x,nb0.y,nb0.z,nb0.w, nb1.x,nb1.y,nb1.z,nb1.w};
            #pragma unroll
            for (int t = 0; t < 8; t++) {
                As[buf][kq + t][lm] = f2tf32(av[t]);
                Bs[buf][kq + t][lm] = f2tf32(bv[t]);
            }
        }
        __syncthreads();
    }

    // epilogue: pairs (c even) -> float2 stores
    #pragma unroll
    for (int mt = 0; mt < 2; mt++) {
        #pragma unroll
        for (int half = 0; half < 2; half++) {
            int r = m0 + m_base + mt * 16 + grp + half * 8;
            if (r >= MROWS) continue;
            int b = 0, n = 0;
            if (EPI == 0) { b = r / NTOK; n = r - b * NTOK; }
            #pragma unroll
            for (int nt = 0; nt < 8; nt++) {
                float2 v = make_float2(acc[mt][nt][half*2], acc[mt][nt][half*2+1]);
                int c = n0 + n_basew + nt * 8 + krw * 2;
                if (EPI == 0) {
                    int part = c / FT;
                    int hc = c - part * FT;            // h*64 + f
                    int hh = hc >> 6, f = hc & 63;
                    size_t o = ((size_t)(b * NH + hh) * NTOK + n) * FH + f;
                    if (part == 0) {
                        *(float2*)&g_q[o] = make_float2((v.x + p0[hc]) * 0.125f,
                                                        (v.y + p0[hc+1]) * 0.125f);
                    } else if (part == 1) {
                        *(float2*)&g_k[o] = v;
                    } else {
                        *(float2*)&g_v[o] = make_float2(v.x + p1[hc], v.y + p1[hc+1]);
                    }
                } else {
                    *(float2*)&outp[(size_t)r * FT + c]
                        = make_float2(v.x + p0[c], v.y + p0[c+1]);
                }
            }
        }
    }
}

// ============================================================
// Fused flash-attention, FFMA2 inner loops, precomputed bias.
// CTA = (b, h, 64-row Q tile), 17 key tiles of 64, online softmax.
// ============================================================
#define KTV_S 68
#define PD_S  130
#define SMEM_ATTN ((64*128 + 64*KTV_S + 64*PD_S) * 4)

__global__ __launch_bounds__(256,2) void attn_kernel()
{
    extern __shared__ float sm[];
    float (*Qd)[128]    = (float(*)[128])sm;
    float (*KtV)[KTV_S] = (float(*)[KTV_S])(sm + 64*128);
    float (*Pd)[PD_S]   = (float(*)[PD_S])(sm + 64*128 + 64*KTV_S);

    const int tid = threadIdx.x;
    const int tx = tid & 15, ty = tid >> 4;
    const int b = blockIdx.z, h = blockIdx.y;
    const int q0 = blockIdx.x * 64;
    const float* Qg = g_q + (size_t)(b * NH + h) * NTOK * FH;
    const float* Kg = g_k + (size_t)(b * NH + h) * NTOK * FH;
    const float* Vg = g_v + (size_t)(b * NH + h) * NTOK * FH;

    const int lrow = tid >> 2;            // 0..63
    const int lfb  = (tid & 3) << 2;      // 0,4,8,12

    // load Q duplicated: Qd[f][2*row]
    #pragma unroll
    for (int s = 0; s < 4; s++) {
        int f = lfb + s * 16;
        float4 v = make_float4(0.f,0.f,0.f,0.f);
        if (q0 + lrow < NTOK)
            v = *(const float4*)(Qg + (size_t)(q0 + lrow) * FH + f);
        float vv[4] = {v.x, v.y, v.z, v.w};
        #pragma unroll
        for (int i = 0; i < 4; i++)
            *(float2*)&Qd[f+i][2*lrow] = make_float2(vv[i], vv[i]);
    }

    unsigned long long O2[4][2];
    float mr[4], ls[4];
    #pragma unroll
    for (int i = 0; i < 4; i++) {
        O2[i][0] = 0ull; O2[i][1] = 0ull;
        mr[i] = -1e30f; ls[i] = 0.f;
    }

    for (int jt = 0; jt < 17; jt++) {
        const int k0 = jt * 64;
        __syncthreads();
        // load K transposed: KtV[f][key]
        #pragma unroll
        for (int s = 0; s < 4; s++) {
            int f = lfb + s * 16;
            float4 v = make_float4(0.f,0.f,0.f,0.f);
            if (k0 + lrow < NTOK)
                v = *(const float4*)(Kg + (size_t)(k0 + lrow) * FH + f);
            KtV[f+0][lrow] = v.x; KtV[f+1][lrow] = v.y;
            KtV[f+2][lrow] = v.z; KtV[f+3][lrow] = v.w;
        }
        __syncthreads();

        // S = Q K^T
        unsigned long long S2[4][2];
        #pragma unroll
        for (int i = 0; i < 4; i++) { S2[i][0] = 0ull; S2[i][1] = 0ull; }
        #pragma unroll 8
        for (int f = 0; f < 64; f++) {
            ulonglong2 qa = *(const ulonglong2*)&Qd[f][ty*8];
            ulonglong2 qb = *(const ulonglong2*)&Qd[f][ty*8 + 4];
            ulonglong2 kk = *(const ulonglong2*)&KtV[f][tx*4];
            unsigned long long av[4] = {qa.x, qa.y, qb.x, qb.y};
            #pragma unroll
            for (int i = 0; i < 4; i++) {
                ffma2(S2[i][0], av[i], kk.x);
                ffma2(S2[i][1], av[i], kk.y);
            }
        }

        // precomputed bias + online softmax + write P (duplicated)
        #pragma unroll
        for (int i = 0; i < 4; i++) {
            int qi = q0 + ty*4 + i;
            float2 u0 = unpack2(S2[i][0]), u1 = unpack2(S2[i][1]);
            float sc[4] = {u0.x, u0.y, u1.x, u1.y};
            float bb[4] = {0.f, 0.f, 0.f, 0.f};
            if (qi < NTOK) {
                float4 bv = *(const float4*)&g_bias[((size_t)h * NTOK + qi) * BPAD
                                                    + k0 + tx*4];
                bb[0] = bv.x; bb[1] = bv.y; bb[2] = bv.z; bb[3] = bv.w;
            }
            #pragma unroll
            for (int j = 0; j < 4; j++) {
                int kj = k0 + tx*4 + j;
                if (qi < NTOK && kj < NTOK) sc[j] += bb[j];
                else                        sc[j] = -1e30f;
            }
            float rm = fmaxf(fmaxf(sc[0], sc[1]), fmaxf(sc[2], sc[3]));
            #pragma unroll
            for (int o = 8; o > 0; o >>= 1)
                rm = fmaxf(rm, __shfl_xor_sync(0xffffffffu, rm, o));
            float mnew = fmaxf(mr[i], rm);
            float alpha = __expf(mr[i] - mnew);
            mr[i] = mnew;
            float rs = 0.f;
            #pragma unroll
            for (int j = 0; j < 4; j++) {
                sc[j] = __expf(sc[j] - mnew);
                rs += sc[j];
            }
            #pragma unroll
            for (int o = 8; o > 0; o >>= 1)
                rs += __shfl_xor_sync(0xffffffffu, rs, o);
            ls[i] = ls[i] * alpha + rs;
            unsigned long long al2 = dup2(alpha);
            mul2(O2[i][0], al2);
            mul2(O2[i][1], al2);
            #pragma unroll
            for (int j = 0; j < 4; j++)
                *(float2*)&Pd[ty*4 + i][2*(tx*4 + j)] = make_float2(sc[j], sc[j]);
        }
        __syncthreads();

        // load V into KtV region as [key][f]
        #pragma unroll
        for (int s = 0; s < 4; s++) {
            int f = lfb + s * 16;
            float4 v = make_float4(0.f,0.f,0.f,0.f);
            if (k0 + lrow < NTOK)
                v = *(const float4*)(Vg + (size_t)(k0 + lrow) * FH + f);
            *(float4*)&KtV[lrow][f] = v;
        }
        __syncthreads();

        // O += P V
        #pragma unroll 8
        for (int k = 0; k < 64; k++) {
            unsigned long long p0 = *(const unsigned long long*)&Pd[ty*4+0][2*k];
            unsigned long long p1 = *(const unsigned long long*)&Pd[ty*4+1][2*k];
            unsigned long long p2 = *(const unsigned long long*)&Pd[ty*4+2][2*k];
            unsigned long long p3 = *(const unsigned long long*)&Pd[ty*4+3][2*k];
            ulonglong2 vv = *(const ulonglong2*)&KtV[k][tx*4];
            ffma2(O2[0][0], p0, vv.x); ffma2(O2[0][1], p0, vv.y);
            ffma2(O2[1][0], p1, vv.x); ffma2(O2[1][1], p1, vv.y);
            ffma2(O2[2][0], p2, vv.x); ffma2(O2[2][1], p2, vv.y);
            ffma2(O2[3][0], p3, vv.x); ffma2(O2[3][1], p3, vv.y);
        }
    }

    // epilogue
    #pragma unroll
    for (int i = 0; i < 4; i++) {
        int qi = q0 + ty*4 + i;
        if (qi >= NTOK) continue;
        float inv = 1.f / ls[i];
        float2 a = unpack2(O2[i][0]);
        float2 c = unpack2(O2[i][1]);
        float* dst = g_ao + (size_t)(b * NTOK + qi) * FT + h * FH + tx*4;
        *(float2*)(dst)     = make_float2(a.x * inv, a.y * inv);
        *(float2*)(dst + 2) = make_float2(c.x * inv, c.y * inv);
    }
}

// ============================================================
extern "C" void kernel_launch(void* const* d_in, const int* in_sizes, int n_in,
                              void* d_out, int out_size)
{
    const float* tokens = (const float*)d_in[0];
    const float* qkv_w  = (const float*)d_in[1];
    const float* q_bias = (const float*)d_in[2];
    const float* v_bias = (const float*)d_in[3];
    const float* table  = (const float*)d_in[4];
    const float* proj_w = (const float*)d_in[5];
    const float* proj_b = (const float*)d_in[6];
    const int*   rpi    = (const int*)d_in[7];
    float* out = (float*)d_out;

    cudaFuncSetAttribute(attn_kernel,
                         cudaFuncAttributeMaxDynamicSharedMemorySize, SMEM_ATTN);

    dim3 blk(256);
    bias_pre<<<dim3(NTOK, NH), blk>>>(table, rpi);

    dim3 g1((3 * FT) / 128, (MROWS + 127) / 128);   // 18 x 65
    gemm_tf32<0><<<g1, blk>>>(tokens, qkv_w, q_bias, v_bias, nullptr);

    dim3 g2((NTOK + 63) / 64, NH, BB);              // 17 x 12 x 8
    attn_kernel<<<g2, blk, SMEM_ATTN>>>();

    dim3 g3(FT / 128, (MROWS + 127) / 128);         // 6 x 65
    gemm_tf32<1><<<g3, blk>>>(nullptr, proj_w, proj_b, nullptr, out);
}

// round 7
// speedup vs baseline: 2.4821x; 1.7727x over previous
#include <cuda_runtime.h>

#define BB    8
#define NH    12
#define NTOK  1025
#define FT    768
#define FH    64
#define MROWS (BB*NTOK)   /* 8200 */
#define BPAD  1088

// ---- static scratch (no allocations allowed) ----
__device__ float g_q[(size_t)BB*NH*NTOK*FH];
__device__ float g_k[(size_t)BB*NH*NTOK*FH];
__device__ float g_v[(size_t)BB*NH*NTOK*FH];
__device__ float g_ao[(size_t)MROWS*FT];
__device__ float g_bias[(size_t)NH*NTOK*BPAD];   /* ~53 MB */

// ---- tf32 helpers ----
__device__ __forceinline__ unsigned f2tf32(float x){
    unsigned r; asm("cvt.rna.tf32.f32 %0, %1;" : "=r"(r) : "f"(x)); return r;
}
__device__ __forceinline__ void mma_tf32(float* c,
        unsigned a0, unsigned a1, unsigned a2, unsigned a3,
        unsigned b0, unsigned b1){
    asm volatile(
        "mma.sync.aligned.m16n8k8.row.col.f32.tf32.tf32.f32 "
        "{%0,%1,%2,%3}, {%4,%5,%6,%7}, {%8,%9}, {%0,%1,%2,%3};"
        : "+f"(c[0]), "+f"(c[1]), "+f"(c[2]), "+f"(c[3])
        : "r"(a0), "r"(a1), "r"(a2), "r"(a3), "r"(b0), "r"(b1));
}
__device__ __forceinline__ void ldsm4(unsigned r[4], const void* p){
    unsigned a = (unsigned)__cvta_generic_to_shared(p);
    asm volatile("ldmatrix.sync.aligned.m8n8.x4.shared.b16 {%0,%1,%2,%3}, [%4];"
        : "=r"(r[0]), "=r"(r[1]), "=r"(r[2]), "=r"(r[3]) : "r"(a));
}

// ============================================================
// Kernel 0: precompute relpos bias  g_bias[h][qi][kj]
// ============================================================
__global__ __launch_bounds__(256) void bias_pre(
        const float* __restrict__ table, const int* __restrict__ rpi)
{
    const int qi = blockIdx.x, h = blockIdx.y;
    const int* row = rpi + (size_t)qi * NTOK;
    float* dst = g_bias + ((size_t)h * NTOK + qi) * BPAD;
    for (int kj = threadIdx.x; kj < NTOK; kj += 256)
        dst[kj] = table[(size_t)row[kj] * NH + h];
}

// ============================================================
// TF32 tensor-core GEMM with LDSM operand loads.
// C[m,c] = sum_k A[m,k] * W[c,k].  CTA 128x128, kslab 16,
// 8 warps (4m x 2n), warp tile 32x64.
// As[m][k], Bs[n][k] both natural row copies (stride 20 -> LDSM conflict-free).
// EPI=0: A=tokens, qkv scatter epilogue.  EPI=1: A=g_ao, proj+bias.
// ============================================================
#define GP 20

template<int EPI>
__global__ __launch_bounds__(256,2) void gemm_tf32(
        const float* __restrict__ Ain, const float* __restrict__ W,
        const float* __restrict__ p0, const float* __restrict__ p1,
        float* __restrict__ outp)
{
    __shared__ unsigned As[2][128][GP];
    __shared__ unsigned Bs[2][128][GP];

    const float* A = (EPI == 0) ? Ain : (const float*)g_ao;

    const int tid  = threadIdx.x;
    const int lane = tid & 31, wid = tid >> 5;
    const int wm = wid & 3, wn = wid >> 2;
    const int m_base = wm * 32, n_base = wn * 64;
    const int grp = lane >> 2, qd = lane & 3;
    const int m0 = blockIdx.y * 128, n0 = blockIdx.x * 128;

    // LDSM per-lane offsets
    const int alr = ((lane >> 3) & 1) * 8 + (lane & 7);  // A row off
    const int alc = (lane >> 4) * 4;                      // A col off
    const int blr = (lane >> 4) * 8 + (lane & 7);         // B row off
    const int blc = ((lane >> 3) & 1) * 4;                // B col off

    const int lm = tid & 127;
    const int kq = (tid >> 7) * 8;
    const float* Ap = A + (size_t)(m0 + lm) * FT + kq;
    const float* Wp = W + (size_t)(n0 + lm) * FT + kq;
    const bool aval = (m0 + lm) < MROWS;

    float acc[2][8][4];
    #pragma unroll
    for (int mt = 0; mt < 2; mt++)
        #pragma unroll
        for (int nt = 0; nt < 8; nt++)
            #pragma unroll
            for (int q = 0; q < 4; q++) acc[mt][nt][q] = 0.f;

    // preload slab 0
    {
        float4 a0 = aval ? *(const float4*)(Ap)     : make_float4(0,0,0,0);
        float4 a1 = aval ? *(const float4*)(Ap + 4) : make_float4(0,0,0,0);
        float4 b0 = *(const float4*)(Wp);
        float4 b1 = *(const float4*)(Wp + 4);
        *(uint4*)&As[0][lm][kq]   = make_uint4(f2tf32(a0.x),f2tf32(a0.y),f2tf32(a0.z),f2tf32(a0.w));
        *(uint4*)&As[0][lm][kq+4] = make_uint4(f2tf32(a1.x),f2tf32(a1.y),f2tf32(a1.z),f2tf32(a1.w));
        *(uint4*)&Bs[0][lm][kq]   = make_uint4(f2tf32(b0.x),f2tf32(b0.y),f2tf32(b0.z),f2tf32(b0.w));
        *(uint4*)&Bs[0][lm][kq+4] = make_uint4(f2tf32(b1.x),f2tf32(b1.y),f2tf32(b1.z),f2tf32(b1.w));
    }
    __syncthreads();

    const int NSTEPS = FT / 16;   // 48
    int buf = 0;
    for (int s = 0; s < NSTEPS; s++) {
        float4 na0, na1, nb0, nb1;
        if (s + 1 < NSTEPS) {
            const float* ap = Ap + (s + 1) * 16;
            const float* wp = Wp + (s + 1) * 16;
            na0 = aval ? *(const float4*)(ap)     : make_float4(0,0,0,0);
            na1 = aval ? *(const float4*)(ap + 4) : make_float4(0,0,0,0);
            nb0 = *(const float4*)(wp);
            nb1 = *(const float4*)(wp + 4);
        }
        #pragma unroll
        for (int ks = 0; ks < 16; ks += 8) {
            unsigned af[2][4];
            #pragma unroll
            for (int mt = 0; mt < 2; mt++)
                ldsm4(af[mt], &As[buf][m_base + mt*16 + alr][ks + alc]);
            #pragma unroll
            for (int p = 0; p < 4; p++) {
                unsigned bf[4];
                ldsm4(bf, &Bs[buf][n_base + p*16 + blr][ks + blc]);
                #pragma unroll
                for (int mt = 0; mt < 2; mt++) {
                    mma_tf32(acc[mt][2*p],   af[mt][0], af[mt][1], af[mt][2], af[mt][3], bf[0], bf[1]);
                    mma_tf32(acc[mt][2*p+1], af[mt][0], af[mt][1], af[mt][2], af[mt][3], bf[2], bf[3]);
                }
            }
        }
        if (s + 1 < NSTEPS) {
            buf ^= 1;
            *(uint4*)&As[buf][lm][kq]   = make_uint4(f2tf32(na0.x),f2tf32(na0.y),f2tf32(na0.z),f2tf32(na0.w));
            *(uint4*)&As[buf][lm][kq+4] = make_uint4(f2tf32(na1.x),f2tf32(na1.y),f2tf32(na1.z),f2tf32(na1.w));
            *(uint4*)&Bs[buf][lm][kq]   = make_uint4(f2tf32(nb0.x),f2tf32(nb0.y),f2tf32(nb0.z),f2tf32(nb0.w));
            *(uint4*)&Bs[buf][lm][kq+4] = make_uint4(f2tf32(nb1.x),f2tf32(nb1.y),f2tf32(nb1.z),f2tf32(nb1.w));
        }
        __syncthreads();
    }

    // epilogue
    #pragma unroll
    for (int mt = 0; mt < 2; mt++) {
        #pragma unroll
        for (int half = 0; half < 2; half++) {
            int r = m0 + m_base + mt * 16 + grp + half * 8;
            if (r >= MROWS) continue;
            int b = 0, n = 0;
            if (EPI == 0) { b = r / NTOK; n = r - b * NTOK; }
            #pragma unroll
            for (int nt = 0; nt < 8; nt++) {
                float2 v = make_float2(acc[mt][nt][half*2], acc[mt][nt][half*2+1]);
                int c = n0 + n_base + nt * 8 + qd * 2;
                if (EPI == 0) {
                    int part = c / FT;
                    int hc = c - part * FT;
                    int hh = hc >> 6, f = hc & 63;
                    size_t o = ((size_t)(b * NH + hh) * NTOK + n) * FH + f;
                    if (part == 0) {
                        *(float2*)&g_q[o] = make_float2((v.x + p0[hc]) * 0.125f,
                                                        (v.y + p0[hc+1]) * 0.125f);
                    } else if (part == 1) {
                        *(float2*)&g_k[o] = v;
                    } else {
                        *(float2*)&g_v[o] = make_float2(v.x + p1[hc], v.y + p1[hc+1]);
                    }
                } else {
                    *(float2*)&outp[(size_t)r * FT + c]
                        = make_float2(v.x + p0[c], v.y + p0[c+1]);
                }
            }
        }
    }
}

// ============================================================
// TF32+LDSM flash attention.  CTA = (b,h,64-q-rows), 8 warps 4x2,
// warp tile 16(q) x 32.  17 key tiles of 64, online softmax.
// Qs[q][f], Ks[key][f] natural; Vs[f][key] transposed; Ps[q][key].
// ============================================================
#define AP 76
#define SMEM_ATTN ((4*64*AP + 64) * 4)

__global__ __launch_bounds__(256,2) void attn_tc()
{
    extern __shared__ float smx[];
    unsigned (*Qs)[AP] = (unsigned(*)[AP])smx;
    unsigned (*Ks)[AP] = (unsigned(*)[AP])(smx + 64*AP);
    unsigned (*Vs)[AP] = (unsigned(*)[AP])(smx + 2*64*AP);
    float    (*Ps)[AP] = (float   (*)[AP])(smx + 3*64*AP);
    float* red = smx + 4*64*AP;   // alpha[64], then lsum[64]

    const int tid = threadIdx.x;
    const int lane = tid & 31, wid = tid >> 5;
    const int wm = wid & 3, wn = wid >> 2;
    const int grp = lane >> 2, qd = lane & 3;
    const int b = blockIdx.z, h = blockIdx.y;
    const int q0 = blockIdx.x * 64;

    const int alr = ((lane >> 3) & 1) * 8 + (lane & 7);
    const int alc = (lane >> 4) * 4;
    const int blr = (lane >> 4) * 8 + (lane & 7);
    const int blc = ((lane >> 3) & 1) * 4;

    const float* Qg = g_q + (size_t)(b * NH + h) * NTOK * FH;
    const float* Kg = g_k + (size_t)(b * NH + h) * NTOK * FH;
    const float* Vg = g_v + (size_t)(b * NH + h) * NTOK * FH;

    const int lrow = tid >> 2;            // 0..63 loader row / softmax row
    const int lfb  = (tid & 3) << 2;      // 0,4,8,12
    const int sq   = tid & 3;             // softmax quarter

    // load Q -> Qs[q][f] (tf32)
    #pragma unroll
    for (int s = 0; s < 4; s++) {
        int f = lfb + 16 * s;
        float4 v = make_float4(0.f,0.f,0.f,0.f);
        if (q0 + lrow < NTOK)
            v = *(const float4*)(Qg + (size_t)(q0 + lrow) * FH + f);
        *(uint4*)&Qs[lrow][f] = make_uint4(f2tf32(v.x),f2tf32(v.y),f2tf32(v.z),f2tf32(v.w));
    }

    float oacc[4][4];
    #pragma unroll
    for (int nt = 0; nt < 4; nt++)
        #pragma unroll
        for (int q = 0; q < 4; q++) oacc[nt][q] = 0.f;
    float mr = -1e30f, ls = 0.f;

    // prefetch tile 0 K/V
    float4 kr[4], vr[4];
    #pragma unroll
    for (int s = 0; s < 4; s++) {
        int f = lfb + 16 * s;
        kr[s] = make_float4(0.f,0.f,0.f,0.f);
        vr[s] = make_float4(0.f,0.f,0.f,0.f);
        if (lrow < NTOK) {
            kr[s] = *(const float4*)(Kg + (size_t)lrow * FH + f);
            vr[s] = *(const float4*)(Vg + (size_t)lrow * FH + f);
        }
    }

    for (int jt = 0; jt < 17; jt++) {
        const int k0 = jt * 64;
        __syncthreads();                                   // (A)
        // store K natural, V transposed (tf32)
        #pragma unroll
        for (int s = 0; s < 4; s++) {
            int f = lfb + 16 * s;
            *(uint4*)&Ks[lrow][f] = make_uint4(f2tf32(kr[s].x),f2tf32(kr[s].y),
                                               f2tf32(kr[s].z),f2tf32(kr[s].w));
            Vs[f+0][lrow] = f2tf32(vr[s].x);
            Vs[f+1][lrow] = f2tf32(vr[s].y);
            Vs[f+2][lrow] = f2tf32(vr[s].z);
            Vs[f+3][lrow] = f2tf32(vr[s].w);
        }
        __syncthreads();                                   // (B)

        // S = Q K^T
        float sacc[4][4];
        #pragma unroll
        for (int nt = 0; nt < 4; nt++)
            #pragma unroll
            for (int q = 0; q < 4; q++) sacc[nt][q] = 0.f;
        #pragma unroll
        for (int kb = 0; kb < 64; kb += 8) {
            unsigned af[4];
            ldsm4(af, &Qs[wm*16 + alr][kb + alc]);
            #pragma unroll
            for (int p = 0; p < 2; p++) {
                unsigned bf[4];
                ldsm4(bf, &Ks[wn*32 + p*16 + blr][kb + blc]);
                mma_tf32(sacc[2*p],   af[0], af[1], af[2], af[3], bf[0], bf[1]);
                mma_tf32(sacc[2*p+1], af[0], af[1], af[2], af[3], bf[2], bf[3]);
            }
        }
        // S frags -> Ps (float)
        #pragma unroll
        for (int nt = 0; nt < 4; nt++) {
            int col = wn*32 + nt*8 + 2*qd;
            *(float2*)&Ps[wm*16 + grp][col]     = make_float2(sacc[nt][0], sacc[nt][1]);
            *(float2*)&Ps[wm*16 + grp + 8][col] = make_float2(sacc[nt][2], sacc[nt][3]);
        }
        __syncthreads();                                   // (C)

        // softmax: thread owns (row=lrow, cols sq*16..+15)
        {
            int qi = q0 + lrow;
            float sc[16];
            const float4* pr = (const float4*)&Ps[lrow][sq*16];
            #pragma unroll
            for (int t = 0; t < 4; t++) {
                float4 v = pr[t];
                sc[4*t]=v.x; sc[4*t+1]=v.y; sc[4*t+2]=v.z; sc[4*t+3]=v.w;
            }
            if (qi < NTOK) {
                const float4* bp = (const float4*)&g_bias[((size_t)h*NTOK + qi)*BPAD + k0 + sq*16];
                #pragma unroll
                for (int t = 0; t < 4; t++) {
                    float4 v = bp[t];
                    sc[4*t]+=v.x; sc[4*t+1]+=v.y; sc[4*t+2]+=v.z; sc[4*t+3]+=v.w;
                }
            }
            #pragma unroll
            for (int j = 0; j < 16; j++)
                if (k0 + sq*16 + j >= NTOK) sc[j] = -1e30f;
            float rm = sc[0];
            #pragma unroll
            for (int j = 1; j < 16; j++) rm = fmaxf(rm, sc[j]);
            rm = fmaxf(rm, __shfl_xor_sync(0xffffffffu, rm, 1));
            rm = fmaxf(rm, __shfl_xor_sync(0xffffffffu, rm, 2));
            float mnew = fmaxf(mr, rm);
            float alpha = __expf(mr - mnew);
            mr = mnew;
            float rs = 0.f;
            #pragma unroll
            for (int j = 0; j < 16; j++) { sc[j] = __expf(sc[j] - mnew); rs += sc[j]; }
            rs += __shfl_xor_sync(0xffffffffu, rs, 1);
            rs += __shfl_xor_sync(0xffffffffu, rs, 2);
            ls = ls * alpha + rs;
            if (sq == 0) red[lrow] = alpha;
            unsigned* pw = (unsigned*)&Ps[lrow][sq*16];
            #pragma unroll
            for (int j = 0; j < 16; j++) pw[j] = f2tf32(sc[j]);
        }
        // prefetch next tile K/V
        if (jt < 16) {
            int kn = k0 + 64 + lrow;
            #pragma unroll
            for (int s = 0; s < 4; s++) {
                int f = lfb + 16 * s;
                kr[s] = make_float4(0.f,0.f,0.f,0.f);
                vr[s] = make_float4(0.f,0.f,0.f,0.f);
                if (kn < NTOK) {
                    kr[s] = *(const float4*)(Kg + (size_t)kn * FH + f);
                    vr[s] = *(const float4*)(Vg + (size_t)kn * FH + f);
                }
            }
        }
        __syncthreads();                                   // (D)

        // O = O*alpha + P V
        float alo = red[wm*16 + grp], ahi = red[wm*16 + grp + 8];
        #pragma unroll
        for (int nt = 0; nt < 4; nt++) {
            oacc[nt][0] *= alo; oacc[nt][1] *= alo;
            oacc[nt][2] *= ahi; oacc[nt][3] *= ahi;
        }
        #pragma unroll
        for (int kb = 0; kb < 64; kb += 8) {
            unsigned af[4];
            ldsm4(af, (const unsigned*)&Ps[wm*16 + alr][kb + alc]);
            #pragma unroll
            for (int p = 0; p < 2; p++) {
                unsigned bf[4];
                ldsm4(bf, &Vs[wn*32 + p*16 + blr][kb + blc]);
                mma_tf32(oacc[2*p],   af[0], af[1], af[2], af[3], bf[0], bf[1]);
                mma_tf32(oacc[2*p+1], af[0], af[1], af[2], af[3], bf[2], bf[3]);
            }
        }
    }

    __syncthreads();
    if (sq == 0) red[lrow] = ls;
    __syncthreads();

    // epilogue: normalize + store
    float ilo = 1.f / red[wm*16 + grp];
    float ihi = 1.f / red[wm*16 + grp + 8];
    int qlo = q0 + wm*16 + grp, qhi = qlo + 8;
    #pragma unroll
    for (int nt = 0; nt < 4; nt++) {
        int col = wn*32 + nt*8 + 2*qd;
        if (qlo < NTOK)
            *(float2*)&g_ao[(size_t)(b * NTOK + qlo) * FT + h * FH + col]
                = make_float2(oacc[nt][0] * ilo, oacc[nt][1] * ilo);
        if (qhi < NTOK)
            *(float2*)&g_ao[(size_t)(b * NTOK + qhi) * FT + h * FH + col]
                = make_float2(oacc[nt][2] * ihi, oacc[nt][3] * ihi);
    }
}

// ============================================================
extern "C" void kernel_launch(void* const* d_in, const int* in_sizes, int n_in,
                              void* d_out, int out_size)
{
    const float* tokens = (const float*)d_in[0];
    const float* qkv_w  = (const float*)d_in[1];
    const float* q_bias = (const float*)d_in[2];
    const float* v_bias = (const float*)d_in[3];
    const float* table  = (const float*)d_in[4];
    const float* proj_w = (const float*)d_in[5];
    const float* proj_b = (const float*)d_in[6];
    const int*   rpi    = (const int*)d_in[7];
    float* out = (float*)d_out;

    cudaFuncSetAttribute(attn_tc,
                         cudaFuncAttributeMaxDynamicSharedMemorySize, SMEM_ATTN);

    dim3 blk(256);
    bias_pre<<<dim3(NTOK, NH), blk>>>(table, rpi);

    dim3 g1((3 * FT) / 128, (MROWS + 127) / 128);   // 18 x 65
    gemm_tf32<0><<<g1, blk>>>(tokens, qkv_w, q_bias, v_bias, nullptr);

    dim3 g2((NTOK + 63) / 64, NH, BB);              // 17 x 12 x 8
    attn_tc<<<g2, blk, SMEM_ATTN>>>();

    dim3 g3(FT / 128, (MROWS + 127) / 128);         // 6 x 65
    gemm_tf32<1><<<g3, blk>>>(nullptr, proj_w, proj_b, nullptr, out);
}

// round 8
// speedup vs baseline: 2.6654x; 1.0738x over previous
#include <cuda_runtime.h>

#define BB    8
#define NH    12
#define NTOK  1025
#define FT    768
#define FH    64
#define MROWS (BB*NTOK)   /* 8200 */
#define BPAD  1088

// ---- static scratch (no allocations allowed) ----
__device__ float g_q[(size_t)BB*NH*NTOK*FH];
__device__ float g_k[(size_t)BB*NH*NTOK*FH];
__device__ float g_v[(size_t)BB*NH*NTOK*FH];
__device__ float g_ao[(size_t)MROWS*FT];
__device__ float g_bias[(size_t)NH*NTOK*BPAD];     /* ~53 MB */
__device__ float g_t32[(size_t)MROWS*FT];          /* tokens, tf32-rounded */
__device__ float g_wq32[(size_t)3*FT*FT];          /* qkv_w,  tf32-rounded */
__device__ float g_wp32[(size_t)FT*FT];            /* proj_w, tf32-rounded */

// ---- tf32 helpers ----
__device__ __forceinline__ unsigned f2tf32(float x){
    unsigned r; asm("cvt.rna.tf32.f32 %0, %1;" : "=r"(r) : "f"(x)); return r;
}
__device__ __forceinline__ void mma_tf32(float* c,
        unsigned a0, unsigned a1, unsigned a2, unsigned a3,
        unsigned b0, unsigned b1){
    asm volatile(
        "mma.sync.aligned.m16n8k8.row.col.f32.tf32.tf32.f32 "
        "{%0,%1,%2,%3}, {%4,%5,%6,%7}, {%8,%9}, {%0,%1,%2,%3};"
        : "+f"(c[0]), "+f"(c[1]), "+f"(c[2]), "+f"(c[3])
        : "r"(a0), "r"(a1), "r"(a2), "r"(a3), "r"(b0), "r"(b1));
}
__device__ __forceinline__ void ldsm4(unsigned r[4], const void* p){
    unsigned a = (unsigned)__cvta_generic_to_shared(p);
    asm volatile("ldmatrix.sync.aligned.m8n8.x4.shared.b16 {%0,%1,%2,%3}, [%4];"
        : "=r"(r[0]), "=r"(r[1]), "=r"(r[2]), "=r"(r[3]) : "r"(a));
}
// ---- cp.async helpers ----
__device__ __forceinline__ void cpasync16(unsigned saddr, const void* g, bool pred){
    int sz = pred ? 16 : 0;
    asm volatile("cp.async.cg.shared.global [%0], [%1], 16, %2;"
        :: "r"(saddr), "l"(g), "r"(sz) : "memory");
}
__device__ __forceinline__ void cp_commit(){
    asm volatile("cp.async.commit_group;" ::: "memory");
}
template<int N> __device__ __forceinline__ void cp_wait(){
    asm volatile("cp.async.wait_group %0;" :: "n"(N) : "memory");
}

// ============================================================
// Kernel A: pre-round tokens / qkv_w / proj_w to tf32 (rna)
// ============================================================
__global__ __launch_bounds__(256) void cvt_pre(
        const float* __restrict__ t, const float* __restrict__ w1,
        const float* __restrict__ w2)
{
    const int stride = gridDim.x * blockDim.x;
    int tid = blockIdx.x * blockDim.x + threadIdx.x;
    const int N1 = MROWS*FT/4, N2 = 3*FT*FT/4, N3 = FT*FT/4;
    for (int i = tid; i < N1; i += stride) {
        float4 v = ((const float4*)t)[i];
        ((uint4*)g_t32)[i] = make_uint4(f2tf32(v.x),f2tf32(v.y),f2tf32(v.z),f2tf32(v.w));
    }
    for (int i = tid; i < N2; i += stride) {
        float4 v = ((const float4*)w1)[i];
        ((uint4*)g_wq32)[i] = make_uint4(f2tf32(v.x),f2tf32(v.y),f2tf32(v.z),f2tf32(v.w));
    }
    for (int i = tid; i < N3; i += stride) {
        float4 v = ((const float4*)w2)[i];
        ((uint4*)g_wp32)[i] = make_uint4(f2tf32(v.x),f2tf32(v.y),f2tf32(v.z),f2tf32(v.w));
    }
}

// ============================================================
// Kernel 0: precompute relpos bias  g_bias[h][qi][kj]
// ============================================================
__global__ __launch_bounds__(256) void bias_pre(
        const float* __restrict__ table, const int* __restrict__ rpi)
{
    const int qi = blockIdx.x, h = blockIdx.y;
    const int* row = rpi + (size_t)qi * NTOK;
    float* dst = g_bias + ((size_t)h * NTOK + qi) * BPAD;
    for (int kj = threadIdx.x; kj < NTOK; kj += 256)
        dst[kj] = table[(size_t)row[kj] * NH + h];
}

// ============================================================
// TF32 tensor-core GEMM, cp.async 4-stage pipeline + LDSM.
// C[m,c] = sum_k A[m,k] * W[c,k].  CTA 128x128, kslab 16,
// 8 warps (4m x 2n), warp tile 32x64.  A/W pre-rounded tf32.
// EPI=0: A=g_t32, W=g_wq32, qkv scatter epilogue.
// EPI=1: A=g_ao (pre-rounded by attn), W=g_wp32, proj+bias.
// ============================================================
#define GP 20
#define NS 4
#define STAGE_U (128*GP)                  /* uints per stage per matrix */
#define SMEM_G  (NS*2*STAGE_U*4)          /* 81920 bytes */

template<int EPI>
__global__ __launch_bounds__(256,2) void gemm_tf32(
        const float* __restrict__ p0, const float* __restrict__ p1,
        float* __restrict__ outp)
{
    extern __shared__ unsigned gsm[];

    const float* A = (EPI == 0) ? (const float*)g_t32 : (const float*)g_ao;
    const float* W = (EPI == 0) ? (const float*)g_wq32 : (const float*)g_wp32;

    const int tid  = threadIdx.x;
    const int lane = tid & 31, wid = tid >> 5;
    const int wm = wid & 3, wn = wid >> 2;
    const int m_base = wm * 32, n_base = wn * 64;
    const int grp = lane >> 2, qd = lane & 3;
    const int m0 = blockIdx.y * 128, n0 = blockIdx.x * 128;

    const int alr = ((lane >> 3) & 1) * 8 + (lane & 7);
    const int alc = (lane >> 4) * 4;
    const int blr = (lane >> 4) * 8 + (lane & 7);
    const int blc = ((lane >> 3) & 1) * 4;

    const int lm = tid & 127;
    const int kq = (tid >> 7) * 8;
    const float* Ap = A + (size_t)(m0 + lm) * FT + kq;
    const float* Wp = W + (size_t)(n0 + lm) * FT + kq;
    const bool aval = (m0 + lm) < MROWS;

    const unsigned sbase = (unsigned)__cvta_generic_to_shared(gsm);
    const unsigned aAddr = sbase + lm * (GP*4) + kq * 4;
    const unsigned bAddr = sbase + NS * STAGE_U * 4 + lm * (GP*4) + kq * 4;

    float acc[2][8][4];
    #pragma unroll
    for (int mt = 0; mt < 2; mt++)
        #pragma unroll
        for (int nt = 0; nt < 8; nt++)
            #pragma unroll
            for (int q = 0; q < 4; q++) acc[mt][nt][q] = 0.f;

    const int NSTEPS = FT / 16;   // 48

    // prologue: fill stages 0..NS-2
    #pragma unroll
    for (int p = 0; p < NS-1; p++) {
        unsigned sa = aAddr + p * STAGE_U * 4;
        unsigned sb = bAddr + p * STAGE_U * 4;
        cpasync16(sa,      Ap + p*16,     aval);
        cpasync16(sa + 16, Ap + p*16 + 4, aval);
        cpasync16(sb,      Wp + p*16,     true);
        cpasync16(sb + 16, Wp + p*16 + 4, true);
        cp_commit();
    }

    for (int s = 0; s < NSTEPS; s++) {
        cp_wait<NS-2>();
        __syncthreads();

        // issue slab s+NS-1 into stage (s+NS-1)%NS (freed at iter s-1)
        int nxt = s + NS - 1;
        if (nxt < NSTEPS) {
            int st = nxt & (NS-1);
            unsigned sa = aAddr + st * STAGE_U * 4;
            unsigned sb = bAddr + st * STAGE_U * 4;
            cpasync16(sa,      Ap + nxt*16,     aval);
            cpasync16(sa + 16, Ap + nxt*16 + 4, aval);
            cpasync16(sb,      Wp + nxt*16,     true);
            cpasync16(sb + 16, Wp + nxt*16 + 4, true);
        }
        cp_commit();   // commit every iteration (empty groups keep count consistent)

        const int st = s & (NS-1);
        unsigned (*Asb)[GP] = (unsigned(*)[GP])(gsm + st * STAGE_U);
        unsigned (*Bsb)[GP] = (unsigned(*)[GP])(gsm + (NS + st) * STAGE_U);

        #pragma unroll
        for (int ks = 0; ks < 16; ks += 8) {
            unsigned af[2][4];
            #pragma unroll
            for (int mt = 0; mt < 2; mt++)
                ldsm4(af[mt], &Asb[m_base + mt*16 + alr][ks + alc]);
            #pragma unroll
            for (int p = 0; p < 4; p++) {
                unsigned bf[4];
                ldsm4(bf, &Bsb[n_base + p*16 + blr][ks + blc]);
                #pragma unroll
                for (int mt = 0; mt < 2; mt++) {
                    mma_tf32(acc[mt][2*p],   af[mt][0], af[mt][1], af[mt][2], af[mt][3], bf[0], bf[1]);
                    mma_tf32(acc[mt][2*p+1], af[mt][0], af[mt][1], af[mt][2], af[mt][3], bf[2], bf[3]);
                }
            }
        }
    }

    // epilogue
    #pragma unroll
    for (int mt = 0; mt < 2; mt++) {
        #pragma unroll
        for (int half = 0; half < 2; half++) {
            int r = m0 + m_base + mt * 16 + grp + half * 8;
            if (r >= MROWS) continue;
            int b = 0, n = 0;
            if (EPI == 0) { b = r / NTOK; n = r - b * NTOK; }
            #pragma unroll
            for (int nt = 0; nt < 8; nt++) {
                float2 v = make_float2(acc[mt][nt][half*2], acc[mt][nt][half*2+1]);
                int c = n0 + n_base + nt * 8 + qd * 2;
                if (EPI == 0) {
                    int part = c / FT;
                    int hc = c - part * FT;
                    int hh = hc >> 6, f = hc & 63;
                    size_t o = ((size_t)(b * NH + hh) * NTOK + n) * FH + f;
                    if (part == 0) {
                        *(float2*)&g_q[o] = make_float2((v.x + p0[hc]) * 0.125f,
                                                        (v.y + p0[hc+1]) * 0.125f);
                    } else if (part == 1) {
                        *(float2*)&g_k[o] = v;
                    } else {
                        *(float2*)&g_v[o] = make_float2(v.x + p1[hc], v.y + p1[hc+1]);
                    }
                } else {
                    *(float2*)&outp[(size_t)r * FT + c]
                        = make_float2(v.x + p0[c], v.y + p0[c+1]);
                }
            }
        }
    }
}

// ============================================================
// TF32+LDSM flash attention (unchanged from R7 except g_ao is
// written tf32-rounded so the proj GEMM can cp.async it raw).
// ============================================================
#define AP 76
#define SMEM_ATTN ((4*64*AP + 64) * 4)

__global__ __launch_bounds__(256,2) void attn_tc()
{
    extern __shared__ float smx[];
    unsigned (*Qs)[AP] = (unsigned(*)[AP])smx;
    unsigned (*Ks)[AP] = (unsigned(*)[AP])(smx + 64*AP);
    unsigned (*Vs)[AP] = (unsigned(*)[AP])(smx + 2*64*AP);
    float    (*Ps)[AP] = (float   (*)[AP])(smx + 3*64*AP);
    float* red = smx + 4*64*AP;

    const int tid = threadIdx.x;
    const int lane = tid & 31, wid = tid >> 5;
    const int wm = wid & 3, wn = wid >> 2;
    const int grp = lane >> 2, qd = lane & 3;
    const int b = blockIdx.z, h = blockIdx.y;
    const int q0 = blockIdx.x * 64;

    const int alr = ((lane >> 3) & 1) * 8 + (lane & 7);
    const int alc = (lane >> 4) * 4;
    const int blr = (lane >> 4) * 8 + (lane & 7);
    const int blc = ((lane >> 3) & 1) * 4;

    const float* Qg = g_q + (size_t)(b * NH + h) * NTOK * FH;
    const float* Kg = g_k + (size_t)(b * NH + h) * NTOK * FH;
    const float* Vg = g_v + (size_t)(b * NH + h) * NTOK * FH;

    const int lrow = tid >> 2;
    const int lfb  = (tid & 3) << 2;
    const int sq   = tid & 3;

    #pragma unroll
    for (int s = 0; s < 4; s++) {
        int f = lfb + 16 * s;
        float4 v = make_float4(0.f,0.f,0.f,0.f);
        if (q0 + lrow < NTOK)
            v = *(const float4*)(Qg + (size_t)(q0 + lrow) * FH + f);
        *(uint4*)&Qs[lrow][f] = make_uint4(f2tf32(v.x),f2tf32(v.y),f2tf32(v.z),f2tf32(v.w));
    }

    float oacc[4][4];
    #pragma unroll
    for (int nt = 0; nt < 4; nt++)
        #pragma unroll
        for (int q = 0; q < 4; q++) oacc[nt][q] = 0.f;
    float mr = -1e30f, ls = 0.f;

    float4 kr[4], vr[4];
    #pragma unroll
    for (int s = 0; s < 4; s++) {
        int f = lfb + 16 * s;
        kr[s] = make_float4(0.f,0.f,0.f,0.f);
        vr[s] = make_float4(0.f,0.f,0.f,0.f);
        if (lrow < NTOK) {
            kr[s] = *(const float4*)(Kg + (size_t)lrow * FH + f);
            vr[s] = *(const float4*)(Vg + (size_t)lrow * FH + f);
        }
    }

    for (int jt = 0; jt < 17; jt++) {
        const int k0 = jt * 64;
        __syncthreads();
        #pragma unroll
        for (int s = 0; s < 4; s++) {
            int f = lfb + 16 * s;
            *(uint4*)&Ks[lrow][f] = make_uint4(f2tf32(kr[s].x),f2tf32(kr[s].y),
                                               f2tf32(kr[s].z),f2tf32(kr[s].w));
            Vs[f+0][lrow] = f2tf32(vr[s].x);
            Vs[f+1][lrow] = f2tf32(vr[s].y);
            Vs[f+2][lrow] = f2tf32(vr[s].z);
            Vs[f+3][lrow] = f2tf32(vr[s].w);
        }
        __syncthreads();

        float sacc[4][4];
        #pragma unroll
        for (int nt = 0; nt < 4; nt++)
            #pragma unroll
            for (int q = 0; q < 4; q++) sacc[nt][q] = 0.f;
        #pragma unroll
        for (int kb = 0; kb < 64; kb += 8) {
            unsigned af[4];
            ldsm4(af, &Qs[wm*16 + alr][kb + alc]);
            #pragma unroll
            for (int p = 0; p < 2; p++) {
                unsigned bf[4];
                ldsm4(bf, &Ks[wn*32 + p*16 + blr][kb + blc]);
                mma_tf32(sacc[2*p],   af[0], af[1], af[2], af[3], bf[0], bf[1]);
                mma_tf32(sacc[2*p+1], af[0], af[1], af[2], af[3], bf[2], bf[3]);
            }
        }
        #pragma unroll
        for (int nt = 0; nt < 4; nt++) {
            int col = wn*32 + nt*8 + 2*qd;
            *(float2*)&Ps[wm*16 + grp][col]     = make_float2(sacc[nt][0], sacc[nt][1]);
            *(float2*)&Ps[wm*16 + grp + 8][col] = make_float2(sacc[nt][2], sacc[nt][3]);
        }
        __syncthreads();

        {
            int qi = q0 + lrow;
            float sc[16];
            const float4* pr = (const float4*)&Ps[lrow][sq*16];
            #pragma unroll
            for (int t = 0; t < 4; t++) {
                float4 v = pr[t];
                sc[4*t]=v.x; sc[4*t+1]=v.y; sc[4*t+2]=v.z; sc[4*t+3]=v.w;
            }
            if (qi < NTOK) {
                const float4* bp = (const float4*)&g_bias[((size_t)h*NTOK + qi)*BPAD + k0 + sq*16];
                #pragma unroll
                for (int t = 0; t < 4; t++) {
                    float4 v = bp[t];
                    sc[4*t]+=v.x; sc[4*t+1]+=v.y; sc[4*t+2]+=v.z; sc[4*t+3]+=v.w;
                }
            }
            #pragma unroll
            for (int j = 0; j < 16; j++)
                if (k0 + sq*16 + j >= NTOK) sc[j] = -1e30f;
            float rm = sc[0];
            #pragma unroll
            for (int j = 1; j < 16; j++) rm = fmaxf(rm, sc[j]);
            rm = fmaxf(rm, __shfl_xor_sync(0xffffffffu, rm, 1));
            rm = fmaxf(rm, __shfl_xor_sync(0xffffffffu, rm, 2));
            float mnew = fmaxf(mr, rm);
            float alpha = __expf(mr - mnew);
            mr = mnew;
            float rs = 0.f;
            #pragma unroll
            for (int j = 0; j < 16; j++) { sc[j] = __expf(sc[j] - mnew); rs += sc[j]; }
            rs += __shfl_xor_sync(0xffffffffu, rs, 1);
            rs += __shfl_xor_sync(0xffffffffu, rs, 2);
            ls = ls * alpha + rs;
            if (sq == 0) red[lrow] = alpha;
            unsigned* pw = (unsigned*)&Ps[lrow][sq*16];
            #pragma unroll
            for (int j = 0; j < 16; j++) pw[j] = f2tf32(sc[j]);
        }
        if (jt < 16) {
            int kn = k0 + 64 + lrow;
            #pragma unroll
            for (int s = 0; s < 4; s++) {
                int f = lfb + 16 * s;
                kr[s] = make_float4(0.f,0.f,0.f,0.f);
                vr[s] = make_float4(0.f,0.f,0.f,0.f);
                if (kn < NTOK) {
                    kr[s] = *(const float4*)(Kg + (size_t)kn * FH + f);
                    vr[s] = *(const float4*)(Vg + (size_t)kn * FH + f);
                }
            }
        }
        __syncthreads();

        float alo = red[wm*16 + grp], ahi = red[wm*16 + grp + 8];
        #pragma unroll
        for (int nt = 0; nt < 4; nt++) {
            oacc[nt][0] *= alo; oacc[nt][1] *= alo;
            oacc[nt][2] *= ahi; oacc[nt][3] *= ahi;
        }
        #pragma unroll
        for (int kb = 0; kb < 64; kb += 8) {
            unsigned af[4];
            ldsm4(af, (const unsigned*)&Ps[wm*16 + alr][kb + alc]);
            #pragma unroll
            for (int p = 0; p < 2; p++) {
                unsigned bf[4];
                ldsm4(bf, &Vs[wn*32 + p*16 + blr][kb + blc]);
                mma_tf32(oacc[2*p],   af[0], af[1], af[2], af[3], bf[0], bf[1]);
                mma_tf32(oacc[2*p+1], af[0], af[1], af[2], af[3], bf[2], bf[3]);
            }
        }
    }

    __syncthreads();
    if (sq == 0) red[lrow] = ls;
    __syncthreads();

    // epilogue: normalize + tf32-round + store (proj consumes g_ao raw)
    float ilo = 1.f / red[wm*16 + grp];
    float ihi = 1.f / red[wm*16 + grp + 8];
    int qlo = q0 + wm*16 + grp, qhi = qlo + 8;
    #pragma unroll
    for (int nt = 0; nt < 4; nt++) {
        int col = wn*32 + nt*8 + 2*qd;
        if (qlo < NTOK)
            *(float2*)&g_ao[(size_t)(b * NTOK + qlo) * FT + h * FH + col]
                = make_float2(__uint_as_float(f2tf32(oacc[nt][0] * ilo)),
                              __uint_as_float(f2tf32(oacc[nt][1] * ilo)));
        if (qhi < NTOK)
            *(float2*)&g_ao[(size_t)(b * NTOK + qhi) * FT + h * FH + col]
                = make_float2(__uint_as_float(f2tf32(oacc[nt][2] * ihi)),
                              __uint_as_float(f2tf32(oacc[nt][3] * ihi)));
    }
}

// ============================================================
extern "C" void kernel_launch(void* const* d_in, const int* in_sizes, int n_in,
                              void* d_out, int out_size)
{
    const float* tokens = (const float*)d_in[0];
    const float* qkv_w  = (const float*)d_in[1];
    const float* q_bias = (const float*)d_in[2];
    const float* v_bias = (const float*)d_in[3];
    const float* table  = (const float*)d_in[4];
    const float* proj_w = (const float*)d_in[5];
    const float* proj_b = (const float*)d_in[6];
    const int*   rpi    = (const int*)d_in[7];
    float* out = (float*)d_out;

    cudaFuncSetAttribute(attn_tc,
                         cudaFuncAttributeMaxDynamicSharedMemorySize, SMEM_ATTN);
    cudaFuncSetAttribute(gemm_tf32<0>,
                         cudaFuncAttributeMaxDynamicSharedMemorySize, SMEM_G);
    cudaFuncSetAttribute(gemm_tf32<1>,
                         cudaFuncAttributeMaxDynamicSharedMemorySize, SMEM_G);

    dim3 blk(256);
    cvt_pre<<<1024, blk>>>(tokens, qkv_w, proj_w);
    bias_pre<<<dim3(NTOK, NH), blk>>>(table, rpi);

    dim3 g1((3 * FT) / 128, (MROWS + 127) / 128);   // 18 x 65
    gemm_tf32<0><<<g1, blk, SMEM_G>>>(q_bias, v_bias, nullptr);

    dim3 g2((NTOK + 63) / 64, NH, BB);              // 17 x 12 x 8
    attn_tc<<<g2, blk, SMEM_ATTN>>>();

    dim3 g3(FT / 128, (MROWS + 127) / 128);         // 6 x 65
    gemm_tf32<1><<<g3, blk, SMEM_G>>>(proj_b, nullptr, out);
}

// round 9
// speedup vs baseline: 4.9025x; 1.8393x over previous
#include <cuda_runtime.h>
#include <cuda_fp16.h>

#define BB    8
#define NH    12
#define NTOK  1025
#define FT    768
#define FH    64
#define MROWS (BB*NTOK)   /* 8200 */
#define BPAD  1088

// ---- static scratch (no allocations allowed) ----
__device__ __half g_q [(size_t)BB*NH*NTOK*FH];
__device__ __half g_k [(size_t)BB*NH*NTOK*FH];
__device__ __half g_v [(size_t)BB*NH*NTOK*FH];
__device__ __half g_ao[(size_t)MROWS*FT];
__device__ float  g_bias[(size_t)NH*NTOK*BPAD];     /* ~53 MB, zero-init pad */
__device__ __half g_t16 [(size_t)MROWS*FT];
__device__ __half g_wq16[(size_t)3*FT*FT];
__device__ __half g_wp16[(size_t)FT*FT];

// ---- helpers ----
__device__ __forceinline__ unsigned packh2(float a, float b){
    __half2 h = __floats2half2_rn(a, b);
    return *(unsigned*)&h;
}
__device__ __forceinline__ void mma_f16(float* c,
        unsigned a0, unsigned a1, unsigned a2, unsigned a3,
        unsigned b0, unsigned b1){
    asm volatile(
        "mma.sync.aligned.m16n8k16.row.col.f32.f16.f16.f32 "
        "{%0,%1,%2,%3}, {%4,%5,%6,%7}, {%8,%9}, {%0,%1,%2,%3};"
        : "+f"(c[0]), "+f"(c[1]), "+f"(c[2]), "+f"(c[3])
        : "r"(a0), "r"(a1), "r"(a2), "r"(a3), "r"(b0), "r"(b1));
}
__device__ __forceinline__ void ldsm4h(unsigned r[4], const void* p){
    unsigned a = (unsigned)__cvta_generic_to_shared(p);
    asm volatile("ldmatrix.sync.aligned.m8n8.x4.shared.b16 {%0,%1,%2,%3}, [%4];"
        : "=r"(r[0]), "=r"(r[1]), "=r"(r[2]), "=r"(r[3]) : "r"(a));
}
__device__ __forceinline__ void ldsm4t(unsigned r[4], const void* p){
    unsigned a = (unsigned)__cvta_generic_to_shared(p);
    asm volatile("ldmatrix.sync.aligned.m8n8.x4.trans.shared.b16 {%0,%1,%2,%3}, [%4];"
        : "=r"(r[0]), "=r"(r[1]), "=r"(r[2]), "=r"(r[3]) : "r"(a));
}
__device__ __forceinline__ void cpasync16(unsigned saddr, const void* g, bool pred){
    int sz = pred ? 16 : 0;
    asm volatile("cp.async.cg.shared.global [%0], [%1], 16, %2;"
        :: "r"(saddr), "l"(g), "r"(sz) : "memory");
}
__device__ __forceinline__ void cp_commit(){
    asm volatile("cp.async.commit_group;" ::: "memory");
}
template<int N> __device__ __forceinline__ void cp_wait(){
    asm volatile("cp.async.wait_group %0;" :: "n"(N) : "memory");
}

// ============================================================
// Kernel A: round fp32 inputs to fp16 scratch
// ============================================================
__global__ __launch_bounds__(256) void cvt_pre(
        const float* __restrict__ t, const float* __restrict__ w1,
        const float* __restrict__ w2)
{
    const int stride = gridDim.x * blockDim.x;
    int tid = blockIdx.x * blockDim.x + threadIdx.x;
    const int N1 = MROWS*FT/8, N2 = 3*FT*FT/8, N3 = FT*FT/8;
    for (int i = tid; i < N1; i += stride) {
        float4 a = ((const float4*)t)[2*i], b = ((const float4*)t)[2*i+1];
        ((uint4*)g_t16)[i] = make_uint4(packh2(a.x,a.y),packh2(a.z,a.w),
                                        packh2(b.x,b.y),packh2(b.z,b.w));
    }
    for (int i = tid; i < N2; i += stride) {
        float4 a = ((const float4*)w1)[2*i], b = ((const float4*)w1)[2*i+1];
        ((uint4*)g_wq16)[i] = make_uint4(packh2(a.x,a.y),packh2(a.z,a.w),
                                         packh2(b.x,b.y),packh2(b.z,b.w));
    }
    for (int i = tid; i < N3; i += stride) {
        float4 a = ((const float4*)w2)[2*i], b = ((const float4*)w2)[2*i+1];
        ((uint4*)g_wp16)[i] = make_uint4(packh2(a.x,a.y),packh2(a.z,a.w),
                                         packh2(b.x,b.y),packh2(b.z,b.w));
    }
}

// ============================================================
// Kernel 0: precompute relpos bias  g_bias[h][qi][kj] (fp32)
// ============================================================
__global__ __launch_bounds__(256) void bias_pre(
        const float* __restrict__ table, const int* __restrict__ rpi)
{
    const int qi = blockIdx.x, h = blockIdx.y;
    const int* row = rpi + (size_t)qi * NTOK;
    float* dst = g_bias + ((size_t)h * NTOK + qi) * BPAD;
    for (int kj = threadIdx.x; kj < NTOK; kj += 256)
        dst[kj] = table[(size_t)row[kj] * NH + h];
}

// ============================================================
// FP16 tensor-core GEMM, cp.async 4-stage + LDSM (m16n8k16).
// C[m,c] = sum_k A[m,k]*W[c,k].  CTA 128x128, k-slab 32,
// 8 warps (4m x 2n), warp tile 32x64.
// EPI=0: A=g_t16, W=g_wq16, qkv scatter (half outputs).
// EPI=1: A=g_ao,  W=g_wp16, proj + bias (fp32 output).
// ============================================================
#define GP2 40                              /* halves per row (32+8 pad) */
#define NS 4
#define STAGE_H (128*GP2)                   /* halves per stage per matrix */
#define SMEM_G  (NS*2*STAGE_H*2)            /* 81920 bytes */

template<int EPI>
__global__ __launch_bounds__(256,2) void gemm_f16(
        const float* __restrict__ p0, const float* __restrict__ p1,
        float* __restrict__ outp)
{
    extern __shared__ __half gsm[];

    const __half* A = (EPI == 0) ? (const __half*)g_t16 : (const __half*)g_ao;
    const __half* W = (EPI == 0) ? (const __half*)g_wq16 : (const __half*)g_wp16;

    const int tid  = threadIdx.x;
    const int lane = tid & 31, wid = tid >> 5;
    const int wm = wid & 3, wn = wid >> 2;
    const int m_base = wm * 32, n_base = wn * 64;
    const int grp = lane >> 2, qd = lane & 3;
    const int m0 = blockIdx.y * 128, n0 = blockIdx.x * 128;

    const int alr = (lane & 7) + ((lane >> 3) & 1) * 8;
    const int aco = (lane >> 4) * 8;                    // halves
    const int blr = (lane & 7) + (lane >> 4) * 8;
    const int bco = ((lane >> 3) & 1) * 8;

    const int lrw = tid & 127;
    const int c0i = (tid >> 7) * 2;                     // chunks {0,1} or {2,3}
    const __half* Ap = A + (size_t)(m0 + lrw) * FT;
    const __half* Wp = W + (size_t)(n0 + lrw) * FT;
    const bool aval = (m0 + lrw) < MROWS;

    const unsigned sbase = (unsigned)__cvta_generic_to_shared(gsm);
    const unsigned aAddr = sbase + lrw * (GP2*2) + c0i * 16;
    const unsigned bAddr = sbase + NS * STAGE_H * 2 + lrw * (GP2*2) + c0i * 16;

    float acc[2][8][4];
    #pragma unroll
    for (int mt = 0; mt < 2; mt++)
        #pragma unroll
        for (int nt = 0; nt < 8; nt++)
            #pragma unroll
            for (int q = 0; q < 4; q++) acc[mt][nt][q] = 0.f;

    const int NSTEPS = FT / 32;   // 24

    #pragma unroll
    for (int p = 0; p < NS-1; p++) {
        unsigned sa = aAddr + p * STAGE_H * 2;
        unsigned sb = bAddr + p * STAGE_H * 2;
        #pragma unroll
        for (int j = 0; j < 2; j++) {
            cpasync16(sa + j*16, Ap + p*32 + (c0i+j)*8, aval);
            cpasync16(sb + j*16, Wp + p*32 + (c0i+j)*8, true);
        }
        cp_commit();
    }

    for (int s = 0; s < NSTEPS; s++) {
        cp_wait<NS-2>();
        __syncthreads();

        int nxt = s + NS - 1;
        if (nxt < NSTEPS) {
            int st = nxt & (NS-1);
            unsigned sa = aAddr + st * STAGE_H * 2;
            unsigned sb = bAddr + st * STAGE_H * 2;
            #pragma unroll
            for (int j = 0; j < 2; j++) {
                cpasync16(sa + j*16, Ap + nxt*32 + (c0i+j)*8, aval);
                cpasync16(sb + j*16, Wp + nxt*32 + (c0i+j)*8, true);
            }
        }
        cp_commit();

        const int st = s & (NS-1);
        const __half* Asb = gsm + st * STAGE_H;
        const __half* Bsb = gsm + (NS + st) * STAGE_H;

        #pragma unroll
        for (int ks = 0; ks < 32; ks += 16) {
            unsigned af[2][4];
            #pragma unroll
            for (int mt = 0; mt < 2; mt++)
                ldsm4h(af[mt], Asb + (m_base + mt*16 + alr) * GP2 + ks + aco);
            #pragma unroll
            for (int p = 0; p < 4; p++) {
                unsigned bf[4];
                ldsm4h(bf, Bsb + (n_base + p*16 + blr) * GP2 + ks + bco);
                #pragma unroll
                for (int mt = 0; mt < 2; mt++) {
                    mma_f16(acc[mt][2*p],   af[mt][0], af[mt][1], af[mt][2], af[mt][3], bf[0], bf[1]);
                    mma_f16(acc[mt][2*p+1], af[mt][0], af[mt][1], af[mt][2], af[mt][3], bf[2], bf[3]);
                }
            }
        }
    }

    // epilogue
    #pragma unroll
    for (int mt = 0; mt < 2; mt++) {
        #pragma unroll
        for (int half = 0; half < 2; half++) {
            int r = m0 + m_base + mt * 16 + grp + half * 8;
            if (r >= MROWS) continue;
            int b = 0, n = 0;
            if (EPI == 0) { b = r / NTOK; n = r - b * NTOK; }
            #pragma unroll
            for (int nt = 0; nt < 8; nt++) {
                float2 v = make_float2(acc[mt][nt][half*2], acc[mt][nt][half*2+1]);
                int c = n0 + n_base + nt * 8 + qd * 2;
                if (EPI == 0) {
                    int part = c / FT;
                    int hc = c - part * FT;
                    int hh = hc >> 6, f = hc & 63;
                    size_t o = ((size_t)(b * NH + hh) * NTOK + n) * FH + f;
                    if (part == 0) {
                        *(unsigned*)&g_q[o] = packh2((v.x + p0[hc]) * 0.125f,
                                                     (v.y + p0[hc+1]) * 0.125f);
                    } else if (part == 1) {
                        *(unsigned*)&g_k[o] = packh2(v.x, v.y);
                    } else {
                        *(unsigned*)&g_v[o] = packh2(v.x + p1[hc], v.y + p1[hc+1]);
                    }
                } else {
                    *(float2*)&outp[(size_t)r * FT + c]
                        = make_float2(v.x + p0[c], v.y + p0[c+1]);
                }
            }
        }
    }
}

// ============================================================
// FP16 flash attention: CTA = (b,h,128 q-rows), 8 warps x 16 rows.
// Register-resident P (C-frag == A-frag), ldmatrix.trans for V,
// warp-local softmax, 2 barriers/tile.
// ============================================================
#define KP 72   /* halves stride: 144B, /16 = 9 (odd) -> conflict-free LDSM */

__global__ __launch_bounds__(256,2) void attn_f16()
{
    __shared__ __half Qs[128*KP];
    __shared__ __half Ks[64*KP];
    __shared__ __half Vs[64*KP];

    const int tid = threadIdx.x;
    const int lane = tid & 31, wid = tid >> 5;
    const int grp = lane >> 2, qd = lane & 3;
    const int b = blockIdx.z, h = blockIdx.y;
    const int q0 = blockIdx.x * 128;

    const int alr = (lane & 7) + ((lane >> 3) & 1) * 8;
    const int aco = (lane >> 4) * 8;
    const int blr = (lane & 7) + (lane >> 4) * 8;
    const int bco = ((lane >> 3) & 1) * 8;
    const int vrr = (lane & 7) + ((lane >> 3) & 1) * 8;   // V trans: key offset
    const int vco = (lane >> 4) * 8;                      // V trans: f offset

    const __half* Qg = g_q + (size_t)(b * NH + h) * NTOK * FH;
    const __half* Kg = g_k + (size_t)(b * NH + h) * NTOK * FH;
    const __half* Vg = g_v + (size_t)(b * NH + h) * NTOK * FH;

    // ---- load Q tile (128 rows x 64 halves) ----
    {
        int row = tid >> 1;
        int cb = (tid & 1) * 4;
        const uint4 z = make_uint4(0,0,0,0);
        bool ok = (q0 + row) < NTOK;
        #pragma unroll
        for (int j = 0; j < 4; j++) {
            uint4 v = ok ? *(const uint4*)(Qg + (size_t)(q0 + row) * FH + (cb+j)*8) : z;
            *(uint4*)&Qs[row * KP + (cb+j)*8] = v;
        }
    }

    // ---- prefetch tile 0 K/V ----
    const int krow = tid >> 2;            // 0..63
    const int kcb  = (tid & 3) * 2;       // chunk base (2 chunks of 8 halves)
    uint4 kr[2], vr[2];
    {
        const uint4 z = make_uint4(0,0,0,0);
        bool ok = krow < NTOK;
        #pragma unroll
        for (int j = 0; j < 2; j++) {
            kr[j] = ok ? *(const uint4*)(Kg + (size_t)krow * FH + (kcb+j)*8) : z;
            vr[j] = ok ? *(const uint4*)(Vg + (size_t)krow * FH + (kcb+j)*8) : z;
        }
    }

    float oacc[8][4];
    #pragma unroll
    for (int nt = 0; nt < 8; nt++)
        #pragma unroll
        for (int q = 0; q < 4; q++) oacc[nt][q] = 0.f;
    float mr[2] = {-1e30f, -1e30f};
    float ls[2] = {0.f, 0.f};

    const int qi0 = q0 + wid*16 + grp;
    const int qi1 = qi0 + 8;
    const float* bp0 = g_bias + ((size_t)h * NTOK + qi0) * BPAD + 2*qd;
    const float* bp1 = g_bias + ((size_t)h * NTOK + qi1) * BPAD + 2*qd;

    for (int jt = 0; jt < 17; jt++) {
        const int k0 = jt * 64;
        // store K/V tile
        #pragma unroll
        for (int j = 0; j < 2; j++) {
            *(uint4*)&Ks[krow * KP + (kcb+j)*8] = kr[j];
            *(uint4*)&Vs[krow * KP + (kcb+j)*8] = vr[j];
        }
        __syncthreads();

        // prefetch next tile
        if (jt < 16) {
            int kn = k0 + 64 + krow;
            const uint4 z = make_uint4(0,0,0,0);
            bool ok = kn < NTOK;
            #pragma unroll
            for (int j = 0; j < 2; j++) {
                kr[j] = ok ? *(const uint4*)(Kg + (size_t)kn * FH + (kcb+j)*8) : z;
                vr[j] = ok ? *(const uint4*)(Vg + (size_t)kn * FH + (kcb+j)*8) : z;
            }
        }

        // ---- S = Q K^T  (warp rows wid*16..+15, all 64 keys) ----
        float sacc[8][4];
        #pragma unroll
        for (int nt = 0; nt < 8; nt++)
            #pragma unroll
            for (int q = 0; q < 4; q++) sacc[nt][q] = 0.f;
        #pragma unroll
        for (int ks = 0; ks < 4; ks++) {
            unsigned af[4];
            ldsm4h(af, &Qs[(wid*16 + alr) * KP + ks*16 + aco]);
            #pragma unroll
            for (int p = 0; p < 4; p++) {
                unsigned bf[4];
                ldsm4h(bf, &Ks[(p*16 + blr) * KP + ks*16 + bco]);
                mma_f16(sacc[2*p],   af[0], af[1], af[2], af[3], bf[0], bf[1]);
                mma_f16(sacc[2*p+1], af[0], af[1], af[2], af[3], bf[2], bf[3]);
            }
        }

        // ---- bias + mask + warp-local online softmax ----
        float m0n = -1e30f, m1n = -1e30f;
        #pragma unroll
        for (int nt = 0; nt < 8; nt++) {
            int col = k0 + nt*8 + 2*qd;
            if (qi0 < NTOK) {
                float2 bb = *(const float2*)(bp0 + k0 + nt*8);
                sacc[nt][0] += bb.x; sacc[nt][1] += bb.y;
            }
            if (qi1 < NTOK) {
                float2 bb = *(const float2*)(bp1 + k0 + nt*8);
                sacc[nt][2] += bb.x; sacc[nt][3] += bb.y;
            }
            if (col     >= NTOK) { sacc[nt][0] = -1e30f; sacc[nt][2] = -1e30f; }
            if (col + 1 >= NTOK) { sacc[nt][1] = -1e30f; sacc[nt][3] = -1e30f; }
            m0n = fmaxf(m0n, fmaxf(sacc[nt][0], sacc[nt][1]));
            m1n = fmaxf(m1n, fmaxf(sacc[nt][2], sacc[nt][3]));
        }
        m0n = fmaxf(m0n, __shfl_xor_sync(0xffffffffu, m0n, 1));
        m0n = fmaxf(m0n, __shfl_xor_sync(0xffffffffu, m0n, 2));
        m1n = fmaxf(m1n, __shfl_xor_sync(0xffffffffu, m1n, 1));
        m1n = fmaxf(m1n, __shfl_xor_sync(0xffffffffu, m1n, 2));
        float mx0 = fmaxf(mr[0], m0n), mx1 = fmaxf(mr[1], m1n);
        float al0 = __expf(mr[0] - mx0), al1 = __expf(mr[1] - mx1);
        mr[0] = mx0; mr[1] = mx1;
        float s0 = 0.f, s1 = 0.f;
        #pragma unroll
        for (int nt = 0; nt < 8; nt++) {
            sacc[nt][0] = __expf(sacc[nt][0] - mx0);
            sacc[nt][1] = __expf(sacc[nt][1] - mx0);
            sacc[nt][2] = __expf(sacc[nt][2] - mx1);
            sacc[nt][3] = __expf(sacc[nt][3] - mx1);
            s0 += sacc[nt][0] + sacc[nt][1];
            s1 += sacc[nt][2] + sacc[nt][3];
        }
        s0 += __shfl_xor_sync(0xffffffffu, s0, 1);
        s0 += __shfl_xor_sync(0xffffffffu, s0, 2);
        s1 += __shfl_xor_sync(0xffffffffu, s1, 1);
        s1 += __shfl_xor_sync(0xffffffffu, s1, 2);
        ls[0] = ls[0] * al0 + s0;
        ls[1] = ls[1] * al1 + s1;
        #pragma unroll
        for (int nt = 0; nt < 8; nt++) {
            oacc[nt][0] *= al0; oacc[nt][1] *= al0;
            oacc[nt][2] *= al1; oacc[nt][3] *= al1;
        }

        // ---- O += P V  (P from registers: C-frag == A-frag after pack) ----
        #pragma unroll
        for (int s = 0; s < 4; s++) {
            unsigned a0 = packh2(sacc[2*s][0],   sacc[2*s][1]);
            unsigned a1 = packh2(sacc[2*s][2],   sacc[2*s][3]);
            unsigned a2 = packh2(sacc[2*s+1][0], sacc[2*s+1][1]);
            unsigned a3 = packh2(sacc[2*s+1][2], sacc[2*s+1][3]);
            #pragma unroll
            for (int p = 0; p < 4; p++) {
                unsigned bf[4];
                ldsm4t(bf, &Vs[(s*16 + vrr) * KP + p*16 + vco]);
                mma_f16(oacc[2*p],   a0, a1, a2, a3, bf[0], bf[1]);
                mma_f16(oacc[2*p+1], a0, a1, a2, a3, bf[2], bf[3]);
            }
        }
        __syncthreads();
    }

    // ---- epilogue: normalize, pack half2, store to g_ao ----
    float i0 = 1.f / ls[0], i1 = 1.f / ls[1];
    #pragma unroll
    for (int nt = 0; nt < 8; nt++) {
        int f = nt*8 + 2*qd;
        if (qi0 < NTOK)
            *(unsigned*)&g_ao[(size_t)(b * NTOK + qi0) * FT + h * FH + f]
                = packh2(oacc[nt][0] * i0, oacc[nt][1] * i0);
        if (qi1 < NTOK)
            *(unsigned*)&g_ao[(size_t)(b * NTOK + qi1) * FT + h * FH + f]
                = packh2(oacc[nt][2] * i1, oacc[nt][3] * i1);
    }
}

// ============================================================
extern "C" void kernel_launch(void* const* d_in, const int* in_sizes, int n_in,
                              void* d_out, int out_size)
{
    const float* tokens = (const float*)d_in[0];
    const float* qkv_w  = (const float*)d_in[1];
    const float* q_bias = (const float*)d_in[2];
    const float* v_bias = (const float*)d_in[3];
    const float* table  = (const float*)d_in[4];
    const float* proj_w = (const float*)d_in[5];
    const float* proj_b = (const float*)d_in[6];
    const int*   rpi    = (const int*)d_in[7];
    float* out = (float*)d_out;

    cudaFuncSetAttribute(gemm_f16<0>,
                         cudaFuncAttributeMaxDynamicSharedMemorySize, SMEM_G);
    cudaFuncSetAttribute(gemm_f16<1>,
                         cudaFuncAttributeMaxDynamicSharedMemorySize, SMEM_G);

    dim3 blk(256);
    cvt_pre<<<1024, blk>>>(tokens, qkv_w, proj_w);
    bias_pre<<<dim3(NTOK, NH), blk>>>(table, rpi);

    dim3 g1((3 * FT) / 128, (MROWS + 127) / 128);   // 18 x 65
    gemm_f16<0><<<g1, blk, SMEM_G>>>(q_bias, v_bias, nullptr);

    dim3 g2((NTOK + 127) / 128, NH, BB);            // 9 x 12 x 8
    attn_f16<<<g2, blk>>>();

    dim3 g3(FT / 128, (MROWS + 127) / 128);         // 6 x 65
    gemm_f16<1><<<g3, blk, SMEM_G>>>(proj_b, nullptr, out);
}

// round 10
// speedup vs baseline: 5.4053x; 1.1026x over previous
#include <cuda_runtime.h>
#include <cuda_fp16.h>

#define BB    8
#define NH    12
#define NTOK  1025
#define FT    768
#define FH    64
#define MROWS (BB*NTOK)   /* 8200 */
#define BPAD  1088
#define LOG2E 1.4426950408889634f

// ---- static scratch (no allocations allowed) ----
__device__ __half g_q [(size_t)BB*NH*NTOK*FH];
__device__ __half g_k [(size_t)BB*NH*NTOK*FH];
__device__ __half g_v [(size_t)BB*NH*NTOK*FH];
__device__ __half g_ao[(size_t)MROWS*FT];
__device__ __half g_bias[(size_t)NH*NTOK*BPAD];     /* fp16, pre-scaled by log2e */
__device__ __half g_t16 [(size_t)MROWS*FT];
__device__ __half g_wq16[(size_t)3*FT*FT];
__device__ __half g_wp16[(size_t)FT*FT];

// ---- helpers ----
__device__ __forceinline__ unsigned packh2(float a, float b){
    __half2 h = __floats2half2_rn(a, b);
    return *(unsigned*)&h;
}
__device__ __forceinline__ float ex2(float x){
    float r; asm("ex2.approx.ftz.f32 %0, %1;" : "=f"(r) : "f"(x)); return r;
}
__device__ __forceinline__ void mma_f16(float* c,
        unsigned a0, unsigned a1, unsigned a2, unsigned a3,
        unsigned b0, unsigned b1){
    asm volatile(
        "mma.sync.aligned.m16n8k16.row.col.f32.f16.f16.f32 "
        "{%0,%1,%2,%3}, {%4,%5,%6,%7}, {%8,%9}, {%0,%1,%2,%3};"
        : "+f"(c[0]), "+f"(c[1]), "+f"(c[2]), "+f"(c[3])
        : "r"(a0), "r"(a1), "r"(a2), "r"(a3), "r"(b0), "r"(b1));
}
__device__ __forceinline__ void ldsm4h(unsigned r[4], const void* p){
    unsigned a = (unsigned)__cvta_generic_to_shared(p);
    asm volatile("ldmatrix.sync.aligned.m8n8.x4.shared.b16 {%0,%1,%2,%3}, [%4];"
        : "=r"(r[0]), "=r"(r[1]), "=r"(r[2]), "=r"(r[3]) : "r"(a));
}
__device__ __forceinline__ void ldsm4t(unsigned r[4], const void* p){
    unsigned a = (unsigned)__cvta_generic_to_shared(p);
    asm volatile("ldmatrix.sync.aligned.m8n8.x4.trans.shared.b16 {%0,%1,%2,%3}, [%4];"
        : "=r"(r[0]), "=r"(r[1]), "=r"(r[2]), "=r"(r[3]) : "r"(a));
}
__device__ __forceinline__ void cpasync16(unsigned saddr, const void* g, bool pred){
    int sz = pred ? 16 : 0;
    asm volatile("cp.async.cg.shared.global [%0], [%1], 16, %2;"
        :: "r"(saddr), "l"(g), "r"(sz) : "memory");
}
__device__ __forceinline__ void cp_commit(){
    asm volatile("cp.async.commit_group;" ::: "memory");
}
template<int N> __device__ __forceinline__ void cp_wait(){
    asm volatile("cp.async.wait_group %0;" :: "n"(N) : "memory");
}

// ============================================================
// Kernel A: round fp32 inputs to fp16 scratch
// ============================================================
__global__ __launch_bounds__(256) void cvt_pre(
        const float* __restrict__ t, const float* __restrict__ w1,
        const float* __restrict__ w2)
{
    const int stride = gridDim.x * blockDim.x;
    int tid = blockIdx.x * blockDim.x + threadIdx.x;
    const int N1 = MROWS*FT/8, N2 = 3*FT*FT/8, N3 = FT*FT/8;
    for (int i = tid; i < N1; i += stride) {
        float4 a = ((const float4*)t)[2*i], b = ((const float4*)t)[2*i+1];
        ((uint4*)g_t16)[i] = make_uint4(packh2(a.x,a.y),packh2(a.z,a.w),
                                        packh2(b.x,b.y),packh2(b.z,b.w));
    }
    for (int i = tid; i < N2; i += stride) {
        float4 a = ((const float4*)w1)[2*i], b = ((const float4*)w1)[2*i+1];
        ((uint4*)g_wq16)[i] = make_uint4(packh2(a.x,a.y),packh2(a.z,a.w),
                                         packh2(b.x,b.y),packh2(b.z,b.w));
    }
    for (int i = tid; i < N3; i += stride) {
        float4 a = ((const float4*)w2)[2*i], b = ((const float4*)w2)[2*i+1];
        ((uint4*)g_wp16)[i] = make_uint4(packh2(a.x,a.y),packh2(a.z,a.w),
                                         packh2(b.x,b.y),packh2(b.z,b.w));
    }
}

// ============================================================
// Kernel 0: precompute relpos bias (fp16, pre-scaled by log2e)
// ============================================================
__global__ __launch_bounds__(256) void bias_pre(
        const float* __restrict__ table, const int* __restrict__ rpi)
{
    const int qi = blockIdx.x, h = blockIdx.y;
    const int* row = rpi + (size_t)qi * NTOK;
    __half* dst = g_bias + ((size_t)h * NTOK + qi) * BPAD;
    for (int kj = threadIdx.x; kj < NTOK; kj += 256)
        dst[kj] = __float2half(table[(size_t)row[kj] * NH + h] * LOG2E);
}

// ============================================================
// FP16 tensor-core GEMM, cp.async 4-stage + LDSM (m16n8k16).
// EPI=0: A=g_t16, W=g_wq16, qkv scatter (q scaled by 0.125*log2e).
// EPI=1: A=g_ao,  W=g_wp16, proj + bias (fp32 output).
// ============================================================
#define GP2 40
#define NS 4
#define STAGE_H (128*GP2)
#define SMEM_G  (NS*2*STAGE_H*2)            /* 81920 bytes */

template<int EPI>
__global__ __launch_bounds__(256,2) void gemm_f16(
        const float* __restrict__ p0, const float* __restrict__ p1,
        float* __restrict__ outp)
{
    extern __shared__ __half gsm[];

    const __half* A = (EPI == 0) ? (const __half*)g_t16 : (const __half*)g_ao;
    const __half* W = (EPI == 0) ? (const __half*)g_wq16 : (const __half*)g_wp16;

    const int tid  = threadIdx.x;
    const int lane = tid & 31, wid = tid >> 5;
    const int wm = wid & 3, wn = wid >> 2;
    const int m_base = wm * 32, n_base = wn * 64;
    const int grp = lane >> 2, qd = lane & 3;
    const int m0 = blockIdx.y * 128, n0 = blockIdx.x * 128;

    const int alr = (lane & 7) + ((lane >> 3) & 1) * 8;
    const int aco = (lane >> 4) * 8;
    const int blr = (lane & 7) + (lane >> 4) * 8;
    const int bco = ((lane >> 3) & 1) * 8;

    const int lrw = tid & 127;
    const int c0i = (tid >> 7) * 2;
    const __half* Ap = A + (size_t)(m0 + lrw) * FT;
    const __half* Wp = W + (size_t)(n0 + lrw) * FT;
    const bool aval = (m0 + lrw) < MROWS;

    const unsigned sbase = (unsigned)__cvta_generic_to_shared(gsm);
    const unsigned aAddr = sbase + lrw * (GP2*2) + c0i * 16;
    const unsigned bAddr = sbase + NS * STAGE_H * 2 + lrw * (GP2*2) + c0i * 16;

    float acc[2][8][4];
    #pragma unroll
    for (int mt = 0; mt < 2; mt++)
        #pragma unroll
        for (int nt = 0; nt < 8; nt++)
            #pragma unroll
            for (int q = 0; q < 4; q++) acc[mt][nt][q] = 0.f;

    const int NSTEPS = FT / 32;   // 24

    #pragma unroll
    for (int p = 0; p < NS-1; p++) {
        unsigned sa = aAddr + p * STAGE_H * 2;
        unsigned sb = bAddr + p * STAGE_H * 2;
        #pragma unroll
        for (int j = 0; j < 2; j++) {
            cpasync16(sa + j*16, Ap + p*32 + (c0i+j)*8, aval);
            cpasync16(sb + j*16, Wp + p*32 + (c0i+j)*8, true);
        }
        cp_commit();
    }

    for (int s = 0; s < NSTEPS; s++) {
        cp_wait<NS-2>();
        __syncthreads();

        int nxt = s + NS - 1;
        if (nxt < NSTEPS) {
            int st = nxt & (NS-1);
            unsigned sa = aAddr + st * STAGE_H * 2;
            unsigned sb = bAddr + st * STAGE_H * 2;
            #pragma unroll
            for (int j = 0; j < 2; j++) {
                cpasync16(sa + j*16, Ap + nxt*32 + (c0i+j)*8, aval);
                cpasync16(sb + j*16, Wp + nxt*32 + (c0i+j)*8, true);
            }
        }
        cp_commit();

        const int st = s & (NS-1);
        const __half* Asb = gsm + st * STAGE_H;
        const __half* Bsb = gsm + (NS + st) * STAGE_H;

        #pragma unroll
        for (int ks = 0; ks < 32; ks += 16) {
            unsigned af[2][4];
            #pragma unroll
            for (int mt = 0; mt < 2; mt++)
                ldsm4h(af[mt], Asb + (m_base + mt*16 + alr) * GP2 + ks + aco);
            #pragma unroll
            for (int p = 0; p < 4; p++) {
                unsigned bf[4];
                ldsm4h(bf, Bsb + (n_base + p*16 + blr) * GP2 + ks + bco);
                #pragma unroll
                for (int mt = 0; mt < 2; mt++) {
                    mma_f16(acc[mt][2*p],   af[mt][0], af[mt][1], af[mt][2], af[mt][3], bf[0], bf[1]);
                    mma_f16(acc[mt][2*p+1], af[mt][0], af[mt][1], af[mt][2], af[mt][3], bf[2], bf[3]);
                }
            }
        }
    }

    const float QSC = 0.125f * LOG2E;
    #pragma unroll
    for (int mt = 0; mt < 2; mt++) {
        #pragma unroll
        for (int half = 0; half < 2; half++) {
            int r = m0 + m_base + mt * 16 + grp + half * 8;
            if (r >= MROWS) continue;
            int b = 0, n = 0;
            if (EPI == 0) { b = r / NTOK; n = r - b * NTOK; }
            #pragma unroll
            for (int nt = 0; nt < 8; nt++) {
                float2 v = make_float2(acc[mt][nt][half*2], acc[mt][nt][half*2+1]);
                int c = n0 + n_base + nt * 8 + qd * 2;
                if (EPI == 0) {
                    int part = c / FT;
                    int hc = c - part * FT;
                    int hh = hc >> 6, f = hc & 63;
                    size_t o = ((size_t)(b * NH + hh) * NTOK + n) * FH + f;
                    if (part == 0) {
                        *(unsigned*)&g_q[o] = packh2((v.x + p0[hc]) * QSC,
                                                     (v.y + p0[hc+1]) * QSC);
                    } else if (part == 1) {
                        *(unsigned*)&g_k[o] = packh2(v.x, v.y);
                    } else {
                        *(unsigned*)&g_v[o] = packh2(v.x + p1[hc], v.y + p1[hc+1]);
                    }
                } else {
                    *(float2*)&outp[(size_t)r * FT + c]
                        = make_float2(v.x + p0[c], v.y + p0[c+1]);
                }
            }
        }
    }
}

// ============================================================
// FP16 flash attention, double-buffered K/V (1 barrier/tile),
// fp16 bias, exp2-domain softmax, register-resident P.
// CTA = (b,h,128 q-rows), 8 warps x 16 rows.
// ============================================================
#define KP 72
#define QOFF (128*KP)
#define KVB  (2*64*KP)                       /* halves per buffer (K+V) */
#define SMEM_ATTN ((QOFF + 2*KVB) * 2)       /* 55296 bytes */

__global__ __launch_bounds__(256,2) void attn_f16()
{
    extern __shared__ __half smh[];
    __half* Qs = smh;

    const int tid = threadIdx.x;
    const int lane = tid & 31, wid = tid >> 5;
    const int grp = lane >> 2, qd = lane & 3;
    const int b = blockIdx.z, h = blockIdx.y;
    const int q0 = blockIdx.x * 128;

    const int alr = (lane & 7) + ((lane >> 3) & 1) * 8;
    const int aco = (lane >> 4) * 8;
    const int blr = (lane & 7) + (lane >> 4) * 8;
    const int bco = ((lane >> 3) & 1) * 8;
    const int vrr = (lane & 7) + ((lane >> 3) & 1) * 8;
    const int vco = (lane >> 4) * 8;

    const __half* Qg = g_q + (size_t)(b * NH + h) * NTOK * FH;
    const __half* Kg = g_k + (size_t)(b * NH + h) * NTOK * FH;
    const __half* Vg = g_v + (size_t)(b * NH + h) * NTOK * FH;

    // ---- load Q tile ----
    {
        int row = tid >> 1;
        int cb = (tid & 1) * 4;
        const uint4 z = make_uint4(0,0,0,0);
        bool ok = (q0 + row) < NTOK;
        #pragma unroll
        for (int j = 0; j < 4; j++) {
            uint4 v = ok ? *(const uint4*)(Qg + (size_t)(q0 + row) * FH + (cb+j)*8) : z;
            *(uint4*)&Qs[row * KP + (cb+j)*8] = v;
        }
    }

    // ---- prefetch + store tile 0 K/V into buffer 0 ----
    const int krow = tid >> 2;
    const int kcb  = (tid & 3) * 2;
    uint4 kr[2], vr[2];
    {
        const uint4 z = make_uint4(0,0,0,0);
        bool ok = krow < NTOK;
        #pragma unroll
        for (int j = 0; j < 2; j++) {
            kr[j] = ok ? *(const uint4*)(Kg + (size_t)krow * FH + (kcb+j)*8) : z;
            vr[j] = ok ? *(const uint4*)(Vg + (size_t)krow * FH + (kcb+j)*8) : z;
        }
        __half* K0 = smh + QOFF;
        __half* V0 = K0 + 64*KP;
        #pragma unroll
        for (int j = 0; j < 2; j++) {
            *(uint4*)&K0[krow * KP + (kcb+j)*8] = kr[j];
            *(uint4*)&V0[krow * KP + (kcb+j)*8] = vr[j];
        }
    }
    __syncthreads();

    float oacc[8][4];
    #pragma unroll
    for (int nt = 0; nt < 8; nt++)
        #pragma unroll
        for (int q = 0; q < 4; q++) oacc[nt][q] = 0.f;
    float mr[2] = {-1e30f, -1e30f};
    float ls[2] = {0.f, 0.f};

    const int qi0 = q0 + wid*16 + grp;
    const int qi1 = qi0 + 8;
    const __half* bp0 = g_bias + ((size_t)h * NTOK + qi0) * BPAD + 2*qd;
    const __half* bp1 = g_bias + ((size_t)h * NTOK + qi1) * BPAD + 2*qd;

    for (int jt = 0; jt < 17; jt++) {
        const int k0 = jt * 64;
        const int cur = jt & 1;
        const __half* Ksb = smh + QOFF + cur * KVB;
        const __half* Vsb = Ksb + 64*KP;

        // ---- S = Q K^T ----
        float sacc[8][4];
        #pragma unroll
        for (int nt = 0; nt < 8; nt++)
            #pragma unroll
            for (int q = 0; q < 4; q++) sacc[nt][q] = 0.f;
        #pragma unroll
        for (int ks = 0; ks < 4; ks++) {
            unsigned af[4];
            ldsm4h(af, &Qs[(wid*16 + alr) * KP + ks*16 + aco]);
            #pragma unroll
            for (int p = 0; p < 4; p++) {
                unsigned bf[4];
                ldsm4h(bf, &Ksb[(p*16 + blr) * KP + ks*16 + bco]);
                mma_f16(sacc[2*p],   af[0], af[1], af[2], af[3], bf[0], bf[1]);
                mma_f16(sacc[2*p+1], af[0], af[1], af[2], af[3], bf[2], bf[3]);
            }
        }

        // ---- issue next-tile global loads (latency hidden under softmax) ----
        if (jt < 16) {
            int kn = k0 + 64 + krow;
            const uint4 z = make_uint4(0,0,0,0);
            bool ok = kn < NTOK;
            #pragma unroll
            for (int j = 0; j < 2; j++) {
                kr[j] = ok ? *(const uint4*)(Kg + (size_t)kn * FH + (kcb+j)*8) : z;
                vr[j] = ok ? *(const uint4*)(Vg + (size_t)kn * FH + (kcb+j)*8) : z;
            }
        }

        // ---- bias (fp16) + mask + warp-local online softmax (exp2 domain) ----
        float m0n = -1e30f, m1n = -1e30f;
        #pragma unroll
        for (int nt = 0; nt < 8; nt++) {
            int col = k0 + nt*8 + 2*qd;
            if (qi0 < NTOK) {
                float2 bb = __half22float2(*(const __half2*)(bp0 + k0 + nt*8));
                sacc[nt][0] += bb.x; sacc[nt][1] += bb.y;
            }
            if (qi1 < NTOK) {
                float2 bb = __half22float2(*(const __half2*)(bp1 + k0 + nt*8));
                sacc[nt][2] += bb.x; sacc[nt][3] += bb.y;
            }
            if (col     >= NTOK) { sacc[nt][0] = -1e30f; sacc[nt][2] = -1e30f; }
            if (col + 1 >= NTOK) { sacc[nt][1] = -1e30f; sacc[nt][3] = -1e30f; }
            m0n = fmaxf(m0n, fmaxf(sacc[nt][0], sacc[nt][1]));
            m1n = fmaxf(m1n, fmaxf(sacc[nt][2], sacc[nt][3]));
        }
        m0n = fmaxf(m0n, __shfl_xor_sync(0xffffffffu, m0n, 1));
        m0n = fmaxf(m0n, __shfl_xor_sync(0xffffffffu, m0n, 2));
        m1n = fmaxf(m1n, __shfl_xor_sync(0xffffffffu, m1n, 1));
        m1n = fmaxf(m1n, __shfl_xor_sync(0xffffffffu, m1n, 2));
        float mx0 = fmaxf(mr[0], m0n), mx1 = fmaxf(mr[1], m1n);
        float al0 = ex2(mr[0] - mx0), al1 = ex2(mr[1] - mx1);
        mr[0] = mx0; mr[1] = mx1;
        float s0 = 0.f, s1 = 0.f;
        #pragma unroll
        for (int nt = 0; nt < 8; nt++) {
            sacc[nt][0] = ex2(sacc[nt][0] - mx0);
            sacc[nt][1] = ex2(sacc[nt][1] - mx0);
            sacc[nt][2] = ex2(sacc[nt][2] - mx1);
            sacc[nt][3] = ex2(sacc[nt][3] - mx1);
            s0 += sacc[nt][0] + sacc[nt][1];
            s1 += sacc[nt][2] + sacc[nt][3];
        }
        s0 += __shfl_xor_sync(0xffffffffu, s0, 1);
        s0 += __shfl_xor_sync(0xffffffffu, s0, 2);
        s1 += __shfl_xor_sync(0xffffffffu, s1, 1);
        s1 += __shfl_xor_sync(0xffffffffu, s1, 2);
        ls[0] = ls[0] * al0 + s0;
        ls[1] = ls[1] * al1 + s1;
        #pragma unroll
        for (int nt = 0; nt < 8; nt++) {
            oacc[nt][0] *= al0; oacc[nt][1] *= al0;
            oacc[nt][2] *= al1; oacc[nt][3] *= al1;
        }

        // ---- store next tile into alternate buffer ----
        if (jt < 16) {
            __half* Kn = smh + QOFF + (cur ^ 1) * KVB;
            __half* Vn = Kn + 64*KP;
            #pragma unroll
            for (int j = 0; j < 2; j++) {
                *(uint4*)&Kn[krow * KP + (kcb+j)*8] = kr[j];
                *(uint4*)&Vn[krow * KP + (kcb+j)*8] = vr[j];
            }
        }

        // ---- O += P V ----
        #pragma unroll
        for (int s = 0; s < 4; s++) {
            unsigned a0 = packh2(sacc[2*s][0],   sacc[2*s][1]);
            unsigned a1 = packh2(sacc[2*s][2],   sacc[2*s][3]);
            unsigned a2 = packh2(sacc[2*s+1][0], sacc[2*s+1][1]);
            unsigned a3 = packh2(sacc[2*s+1][2], sacc[2*s+1][3]);
            #pragma unroll
            for (int p = 0; p < 4; p++) {
                unsigned bf[4];
                ldsm4t(bf, &Vsb[(s*16 + vrr) * KP + p*16 + vco]);
                mma_f16(oacc[2*p],   a0, a1, a2, a3, bf[0], bf[1]);
                mma_f16(oacc[2*p+1], a0, a1, a2, a3, bf[2], bf[3]);
            }
        }
        __syncthreads();
    }

    // ---- epilogue ----
    float i0 = 1.f / ls[0], i1 = 1.f / ls[1];
    #pragma unroll
    for (int nt = 0; nt < 8; nt++) {
        int f = nt*8 + 2*qd;
        if (qi0 < NTOK)
            *(unsigned*)&g_ao[(size_t)(b * NTOK + qi0) * FT + h * FH + f]
                = packh2(oacc[nt][0] * i0, oacc[nt][1] * i0);
        if (qi1 < NTOK)
            *(unsigned*)&g_ao[(size_t)(b * NTOK + qi1) * FT + h * FH + f]
                = packh2(oacc[nt][2] * i1, oacc[nt][3] * i1);
    }
}

// ============================================================
extern "C" void kernel_launch(void* const* d_in, const int* in_sizes, int n_in,
                              void* d_out, int out_size)
{
    const float* tokens = (const float*)d_in[0];
    const float* qkv_w  = (const float*)d_in[1];
    const float* q_bias = (const float*)d_in[2];
    const float* v_bias = (const float*)d_in[3];
    const float* table  = (const float*)d_in[4];
    const float* proj_w = (const float*)d_in[5];
    const float* proj_b = (const float*)d_in[6];
    const int*   rpi    = (const int*)d_in[7];
    float* out = (float*)d_out;

    cudaFuncSetAttribute(gemm_f16<0>,
                         cudaFuncAttributeMaxDynamicSharedMemorySize, SMEM_G);
    cudaFuncSetAttribute(gemm_f16<1>,
                         cudaFuncAttributeMaxDynamicSharedMemorySize, SMEM_G);
    cudaFuncSetAttribute(attn_f16,
                         cudaFuncAttributeMaxDynamicSharedMemorySize, SMEM_ATTN);

    dim3 blk(256);
    cvt_pre<<<1024, blk>>>(tokens, qkv_w, proj_w);
    bias_pre<<<dim3(NTOK, NH), blk>>>(table, rpi);

    dim3 g1((3 * FT) / 128, (MROWS + 127) / 128);   // 18 x 65
    gemm_f16<0><<<g1, blk, SMEM_G>>>(q_bias, v_bias, nullptr);

    dim3 g2((NTOK + 127) / 128, NH, BB);            // 9 x 12 x 8
    attn_f16<<<g2, blk, SMEM_ATTN>>>();

    dim3 g3(FT / 128, (MROWS + 127) / 128);         // 6 x 65
    gemm_f16<1><<<g3, blk, SMEM_G>>>(proj_b, nullptr, out);
}